// round 1
// baseline (speedup 1.0000x reference)
#include <cuda_runtime.h>
#include <cstdint>

#define NTHR 256

constexpr int B_  = 2;
constexpr int N_  = 256;
constexpr int DC_ = 96;
constexpr int DP_ = 160;
constexpr int DE_ = 64;
constexpr int H_  = 8;
constexpr int KT  = 32;              // k rows per tile
constexpr int NTILES = N_ / KT;      // 8

// ---------------- device scratch (no allocations allowed) ----------------
__device__ float g_Qc[B_*N_*DC_];   // prescaled by 1/sqrt(96)
__device__ float g_Kc[B_*N_*DC_];
__device__ float g_Vc[B_*N_*DC_];
__device__ float g_Qp[B_*N_*DP_];   // prescaled by 1/sqrt(160)
__device__ float g_Kp[B_*N_*DP_];
__device__ float g_Vp[B_*N_*DP_];
__device__ float g_weperm[(DC_+DP_)*DE_];   // we_out rows permuted to [class96 | param160]

// ---------------- shared memory layout (floats) ----------------
// sQc 96 | sQp 160 | sWV 256 | sScC 2048 | sScP 2048 | sE 2048 | bufA 8192 | bufB 8192 | sW 25760
constexpr int OFF_QC  = 0;
constexpr int OFF_QP  = 96;
constexpr int OFF_WV  = 256;
constexpr int OFF_SCC = 512;
constexpr int OFF_SCP = 2560;
constexpr int OFF_E   = 4608;
constexpr int OFF_A   = 6656;
constexpr int OFF_B   = 14848;
constexpr int OFF_W   = 23040;
constexpr int SMEM_FLOATS = 23040 + 25760;
constexpr int SMEM_BYTES  = SMEM_FLOATS * 4;   // 195200

// ============================= prep kernel =============================
// QKV projections (+Q prescale) and permuted we_out.
__global__ void __launch_bounds__(NTHR) prep_kernel(
    const float* __restrict__ classes, const float* __restrict__ params,
    const float* __restrict__ wc_qkv,  const float* __restrict__ bc_qkv,
    const float* __restrict__ wp_qkv,  const float* __restrict__ bp_qkv,
    const float* __restrict__ we_out)
{
    __shared__ float rc[DC_];
    __shared__ float rp[DP_];
    const int bn = blockIdx.x;
    const int t  = threadIdx.x;
    if (t < DC_) rc[t] = classes[bn*DC_ + t];
    if (t < DP_) rp[t] = params[bn*DP_ + t];
    __syncthreads();

    const float invc = 0.10206207261596575f;   // 1/sqrt(96)
    const float invp = 0.07905694150420949f;   // 1/sqrt(160)

    for (int o = t; o < 3*DC_; o += NTHR) {
        float acc = bc_qkv[o];
        #pragma unroll 4
        for (int i = 0; i < DC_; i++) acc = fmaf(rc[i], wc_qkv[i*3*DC_ + o], acc);
        const int part = o / DC_, d = o - part*DC_;
        if (part == 0)      g_Qc[bn*DC_ + d] = acc * invc;
        else if (part == 1) g_Kc[bn*DC_ + d] = acc;
        else                g_Vc[bn*DC_ + d] = acc;
    }
    for (int o = t; o < 3*DP_; o += NTHR) {
        float acc = bp_qkv[o];
        #pragma unroll 4
        for (int i = 0; i < DP_; i++) acc = fmaf(rp[i], wp_qkv[i*3*DP_ + o], acc);
        const int part = o / DP_, d = o - part*DP_;
        if (part == 0)      g_Qp[bn*DP_ + d] = acc * invp;
        else if (part == 1) g_Kp[bn*DP_ + d] = acc;
        else                g_Vp[bn*DP_ + d] = acc;
    }
    if (blockIdx.x == 0) {
        // new_edges layout: col j = h*32+w ; w<12 -> class[h*12+w], else param[h*20+w-12]
        for (int r = t; r < DC_+DP_; r += NTHR) {
            int src;
            if (r < DC_) src = (r/12)*32 + (r%12);
            else { const int p = r - DC_; src = (p/20)*32 + 12 + (p%20); }
            for (int o = 0; o < DE_; o++) g_weperm[r*DE_ + o] = we_out[src*DE_ + o];
        }
    }
}

// ============================= gemm micro-kernels =============================
// Warp handles 4 rows; lane handles cols lane + 32*j, j < NC. A in smem (broadcast
// float4 loads), W in smem row-major (K x 32*NC or wider via ldw).

template<int KD, int NC>
__device__ __forceinline__ void gemm1(const float* __restrict__ A0, int lda,
                                      const float* __restrict__ W, int ldw,
                                      float acc[4][NC], int lane)
{
    #pragma unroll
    for (int i = 0; i < 4; i++)
        #pragma unroll
        for (int j = 0; j < NC; j++) acc[i][j] = 0.f;

    #pragma unroll 2
    for (int kk = 0; kk < KD; kk += 4) {
        float4 av[4];
        #pragma unroll
        for (int i = 0; i < 4; i++)
            av[i] = *reinterpret_cast<const float4*>(A0 + i*lda + kk);
        #pragma unroll
        for (int u = 0; u < 4; u++) {
            float wv[NC];
            #pragma unroll
            for (int j = 0; j < NC; j++) wv[j] = W[(kk+u)*ldw + lane + 32*j];
            #pragma unroll
            for (int i = 0; i < 4; i++) {
                const float a = (u==0)?av[i].x:(u==1)?av[i].y:(u==2)?av[i].z:av[i].w;
                #pragma unroll
                for (int j = 0; j < NC; j++) acc[i][j] = fmaf(a, wv[j], acc[i][j]);
            }
        }
    }
}

// dual-output version (shared A loads for mul & add weights)
template<int KD, int NC>
__device__ __forceinline__ void gemm2(const float* __restrict__ A0, int lda,
                                      const float* __restrict__ W1,
                                      const float* __restrict__ W2, int ldw,
                                      float aM[4][NC], float aD[4][NC], int lane)
{
    #pragma unroll
    for (int i = 0; i < 4; i++)
        #pragma unroll
        for (int j = 0; j < NC; j++) { aM[i][j] = 0.f; aD[i][j] = 0.f; }

    #pragma unroll 2
    for (int kk = 0; kk < KD; kk += 4) {
        float4 av[4];
        #pragma unroll
        for (int i = 0; i < 4; i++)
            av[i] = *reinterpret_cast<const float4*>(A0 + i*lda + kk);
        #pragma unroll
        for (int u = 0; u < 4; u++) {
            float w1[NC], w2[NC];
            #pragma unroll
            for (int j = 0; j < NC; j++) {
                w1[j] = W1[(kk+u)*ldw + lane + 32*j];
                w2[j] = W2[(kk+u)*ldw + lane + 32*j];
            }
            #pragma unroll
            for (int i = 0; i < 4; i++) {
                const float a = (u==0)?av[i].x:(u==1)?av[i].y:(u==2)?av[i].z:av[i].w;
                #pragma unroll
                for (int j = 0; j < NC; j++) {
                    aM[i][j] = fmaf(a, w1[j], aM[i][j]);
                    aD[i][j] = fmaf(a, w2[j], aD[i][j]);
                }
            }
        }
    }
}

__device__ __forceinline__ void stage_cp(float* dst, const float* __restrict__ src,
                                         int n, int tid)
{
    float4* d4 = reinterpret_cast<float4*>(dst);
    const float4* s4 = reinterpret_cast<const float4*>(src);
    const int n4 = n >> 2;
    for (int i = tid; i < n4; i += NTHR) d4[i] = s4[i];
}

__device__ __forceinline__ float lrelu(float v) { return v > 0.f ? v : 0.05f * v; }

// ============================= fused main kernel =============================
__global__ void __launch_bounds__(NTHR, 1) fused_kernel(
    const float* __restrict__ edges,
    const float* __restrict__ fc_mul_w, const float* __restrict__ fc_mul_b,
    const float* __restrict__ fc_add_w, const float* __restrict__ fc_add_b,
    const float* __restrict__ fc_m1_w,  const float* __restrict__ fc_m1_b,
    const float* __restrict__ fc_m2_w,  const float* __restrict__ fc_m2_b,
    const float* __restrict__ fp_mul_w, const float* __restrict__ fp_mul_b,
    const float* __restrict__ fp_add_w, const float* __restrict__ fp_add_b,
    const float* __restrict__ fp_m1_w,  const float* __restrict__ fp_m1_b,
    const float* __restrict__ fp_m2_w,  const float* __restrict__ fp_m2_b,
    const float* __restrict__ wc_out,   const float* __restrict__ bc_out,
    const float* __restrict__ wp_out,   const float* __restrict__ bp_out,
    const float* __restrict__ be_out,
    float* __restrict__ out)
{
    extern __shared__ float sm[];
    float* sQc  = sm + OFF_QC;
    float* sQp  = sm + OFF_QP;
    float* sWV  = sm + OFF_WV;
    float* sScC = sm + OFF_SCC;
    float* sScP = sm + OFF_SCP;
    float* sE   = sm + OFF_E;
    float* bufA = sm + OFF_A;
    float* bufB = sm + OFF_B;
    float* sW   = sm + OFF_W;

    const int tid  = threadIdx.x;
    const int warp = tid >> 5;
    const int lane = tid & 31;
    const int bq   = blockIdx.x;
    const int b    = bq >> 8;

    for (int i = tid; i < DC_; i += NTHR) sQc[i] = g_Qc[bq*DC_ + i];
    for (int i = tid; i < DP_; i += NTHR) sQp[i] = g_Qp[bq*DP_ + i];

    const float* Eb  = edges + (size_t)bq * N_ * DE_;
    float* outE = out + (size_t)(B_*N_*DC_ + B_*N_*DP_) + (size_t)bq * N_ * DE_;

    const int r0 = warp * 4;   // first of this warp's 4 rows within the tile

    for (int t8 = 0; t8 < NTILES; t8++) {
        const int k0 = t8 * KT;
        __syncthreads();
        // ---- load E tile + class FiLM-linear weights ----
        {
            const float4* src = reinterpret_cast<const float4*>(Eb + (size_t)k0 * DE_);
            float4* dst = reinterpret_cast<float4*>(sE);
            for (int i = tid; i < KT*DE_/4; i += NTHR) dst[i] = src[i];
        }
        stage_cp(sW,          fc_mul_w, DE_*DC_, tid);   // 6144
        stage_cp(sW + 6144,   fc_add_w, DE_*DC_, tid);   // 6144
        stage_cp(sW + 12288,  fc_mul_b, DC_,     tid);
        stage_cp(sW + 12384,  fc_add_b, DC_,     tid);
        __syncthreads();
        // ---- stage 1 class: bufA[:,0:96] = a*mul + add + a ----
        {
            float aM[4][3], aD[4][3];
            gemm2<DE_,3>(sE + r0*DE_, DE_, sW, sW + 6144, DC_, aM, aD, lane);
            const float* mb = sW + 12288;
            const float* ab = sW + 12384;
            #pragma unroll
            for (int i = 0; i < 4; i++) {
                const int r = r0 + i, k = k0 + r;
                const float* Kr = g_Kc + (size_t)(b*N_ + k) * DC_;
                #pragma unroll
                for (int j = 0; j < 3; j++) {
                    const int c = lane + 32*j;
                    const float a = sQc[c] * Kr[c];
                    bufA[r*256 + c] = fmaf(a, aM[i][j] + mb[c], aD[i][j] + ab[c] + a);
                }
            }
        }
        __syncthreads();
        stage_cp(sW,          fp_mul_w, DE_*DP_, tid);   // 10240
        stage_cp(sW + 10240,  fp_add_w, DE_*DP_, tid);
        stage_cp(sW + 20480,  fp_mul_b, DP_,     tid);
        stage_cp(sW + 20640,  fp_add_b, DP_,     tid);
        __syncthreads();
        // ---- stage 1 param: bufA[:,96:256] ----
        {
            float aM[4][5], aD[4][5];
            gemm2<DE_,5>(sE + r0*DE_, DE_, sW, sW + 10240, DP_, aM, aD, lane);
            const float* mb = sW + 20480;
            const float* ab = sW + 20640;
            #pragma unroll
            for (int i = 0; i < 4; i++) {
                const int r = r0 + i, k = k0 + r;
                const float* Kr = g_Kp + (size_t)(b*N_ + k) * DP_;
                #pragma unroll
                for (int j = 0; j < 5; j++) {
                    const int c = lane + 32*j;
                    const float a = sQp[c] * Kr[c];
                    bufA[r*256 + 96 + c] = fmaf(a, aM[i][j] + mb[c], aD[i][j] + ab[c] + a);
                }
            }
        }
        __syncthreads();
        // ---- MLP layer 1, class ----
        stage_cp(sW,        fc_m1_w, DC_*DC_, tid);
        stage_cp(sW + 9216, fc_m1_b, DC_,     tid);
        __syncthreads();
        {
            float acc[4][3];
            gemm1<DC_,3>(bufA + r0*256, 256, sW, DC_, acc, lane);
            const float* bb = sW + 9216;
            #pragma unroll
            for (int i = 0; i < 4; i++)
                #pragma unroll
                for (int j = 0; j < 3; j++) {
                    const int c = lane + 32*j;
                    bufB[(r0+i)*256 + c] = lrelu(acc[i][j] + bb[c]);
                }
        }
        __syncthreads();
        // ---- MLP layer 1, param ----
        stage_cp(sW,         fp_m1_w, DP_*DP_, tid);
        stage_cp(sW + 25600, fp_m1_b, DP_,     tid);
        __syncthreads();
        {
            float acc[4][5];
            gemm1<DP_,5>(bufA + r0*256 + 96, 256, sW, DP_, acc, lane);
            const float* bb = sW + 25600;
            #pragma unroll
            for (int i = 0; i < 4; i++)
                #pragma unroll
                for (int j = 0; j < 5; j++) {
                    const int c = lane + 32*j;
                    bufB[(r0+i)*256 + 96 + c] = lrelu(acc[i][j] + bb[c]);
                }
        }
        __syncthreads();
        // ---- MLP layer 2, class ----
        stage_cp(sW,        fc_m2_w, DC_*DC_, tid);
        stage_cp(sW + 9216, fc_m2_b, DC_,     tid);
        __syncthreads();
        {
            float acc[4][3];
            gemm1<DC_,3>(bufB + r0*256, 256, sW, DC_, acc, lane);
            const float* bb = sW + 9216;
            #pragma unroll
            for (int i = 0; i < 4; i++)
                #pragma unroll
                for (int j = 0; j < 3; j++) {
                    const int c = lane + 32*j;
                    bufA[(r0+i)*256 + c] = lrelu(acc[i][j] + bb[c]);
                }
        }
        __syncthreads();
        // ---- MLP layer 2, param ----
        stage_cp(sW,         fp_m2_w, DP_*DP_, tid);
        stage_cp(sW + 25600, fp_m2_b, DP_,     tid);
        __syncthreads();
        {
            float acc[4][5];
            gemm1<DP_,5>(bufB + r0*256 + 96, 256, sW, DP_, acc, lane);
            const float* bb = sW + 25600;
            #pragma unroll
            for (int i = 0; i < 4; i++)
                #pragma unroll
                for (int j = 0; j < 5; j++) {
                    const int c = lane + 32*j;
                    bufA[(r0+i)*256 + 96 + c] = lrelu(acc[i][j] + bb[c]);
                }
        }
        __syncthreads();
        // ---- per-head score sums (from final y2 in bufA) + stage permuted we_out ----
        for (int tau = tid; tau < KT*H_*2; tau += NTHR) {
            const int r = tau >> 4;
            const int rest = tau & 15;
            const int h = rest >> 1;
            if ((rest & 1) == 0) {
                const float* p = bufA + r*256 + h*12;
                float s = 0.f;
                #pragma unroll
                for (int d = 0; d < 12; d++) s += p[d];
                sScC[(k0 + r)*H_ + h] = s;
            } else {
                const float* p = bufA + r*256 + 96 + h*20;
                float s = 0.f;
                #pragma unroll
                for (int d = 0; d < 20; d++) s += p[d];
                sScP[(k0 + r)*H_ + h] = s;
            }
        }
        stage_cp(sW,         g_weperm, (DC_+DP_)*DE_, tid);  // 16384
        stage_cp(sW + 16384, be_out,   DE_,           tid);
        __syncthreads();
        // ---- out_e = y2_cat(permuted) @ we_out + be ----
        {
            float acc[4][2];
            gemm1<256,2>(bufA + r0*256, 256, sW, DE_, acc, lane);
            const float* bb = sW + 16384;
            #pragma unroll
            for (int i = 0; i < 4; i++) {
                const int k = k0 + r0 + i;
                float* op = outE + (size_t)k * DE_;
                #pragma unroll
                for (int j = 0; j < 2; j++) {
                    const int c = lane + 32*j;
                    op[c] = acc[i][j] + bb[c];
                }
            }
        }
    }
    __syncthreads();

    // ---- softmax over k for each head (warp w owns head w, class then param) ----
    {
        const int h = warp;
        #pragma unroll
        for (int ty = 0; ty < 2; ty++) {
            float* S = ty ? sScP : sScC;
            float m = -1e30f;
            for (int k = lane; k < N_; k += 32) m = fmaxf(m, S[k*H_ + h]);
            #pragma unroll
            for (int o = 16; o; o >>= 1) m = fmaxf(m, __shfl_xor_sync(0xffffffffu, m, o));
            float sum = 0.f;
            for (int k = lane; k < N_; k += 32) {
                const float e = __expf(S[k*H_ + h] - m);
                S[k*H_ + h] = e;
                sum += e;
            }
            #pragma unroll
            for (int o = 16; o; o >>= 1) sum += __shfl_xor_sync(0xffffffffu, sum, o);
            const float inv = 1.f / sum;
            for (int k = lane; k < N_; k += 32) S[k*H_ + h] *= inv;
        }
    }
    __syncthreads();

    // ---- weighted V (cross: ap weights Vc, ac weights Vp) ----
    {
        float acc = 0.f;
        if (tid < DC_) {
            const int c = tid, h = c / 12;
            const float* V = g_Vc + (size_t)(b*N_) * DC_ + c;
            for (int k = 0; k < N_; k++) acc = fmaf(sScP[k*H_ + h], V[(size_t)k*DC_], acc);
        } else {
            const int p = tid - DC_, h = p / 20;
            const float* V = g_Vp + (size_t)(b*N_) * DP_ + p;
            for (int k = 0; k < N_; k++) acc = fmaf(sScC[k*H_ + h], V[(size_t)k*DP_], acc);
        }
        sWV[tid] = acc;
    }
    __syncthreads();

    // ---- output projections ----
    if (tid < DC_) {
        const int o = tid;
        float acc = bc_out[o];
        for (int c = 0; c < DC_; c++) acc = fmaf(sWV[c], wc_out[c*DC_ + o], acc);
        out[(size_t)bq*DC_ + o] = acc;
    } else {
        const int o = tid - DC_;
        float acc = bp_out[o];
        for (int p = 0; p < DP_; p++) acc = fmaf(sWV[DC_ + p], wp_out[p*DP_ + o], acc);
        out[(size_t)(B_*N_*DC_) + (size_t)bq*DP_ + o] = acc;
    }
}

// ============================= launch =============================
extern "C" void kernel_launch(void* const* d_in, const int* in_sizes, int n_in,
                              void* d_out, int out_size)
{
    const float* classes  = (const float*)d_in[0];
    const float* params   = (const float*)d_in[1];
    const float* edges    = (const float*)d_in[2];
    const float* wc_qkv   = (const float*)d_in[3];
    const float* bc_qkv   = (const float*)d_in[4];
    const float* wp_qkv   = (const float*)d_in[5];
    const float* bp_qkv   = (const float*)d_in[6];
    const float* fc_mul_w = (const float*)d_in[7];
    const float* fc_mul_b = (const float*)d_in[8];
    const float* fc_add_w = (const float*)d_in[9];
    const float* fc_add_b = (const float*)d_in[10];
    const float* fc_m1_w  = (const float*)d_in[11];
    const float* fc_m1_b  = (const float*)d_in[12];
    const float* fc_m2_w  = (const float*)d_in[13];
    const float* fc_m2_b  = (const float*)d_in[14];
    const float* fp_mul_w = (const float*)d_in[15];
    const float* fp_mul_b = (const float*)d_in[16];
    const float* fp_add_w = (const float*)d_in[17];
    const float* fp_add_b = (const float*)d_in[18];
    const float* fp_m1_w  = (const float*)d_in[19];
    const float* fp_m1_b  = (const float*)d_in[20];
    const float* fp_m2_w  = (const float*)d_in[21];
    const float* fp_m2_b  = (const float*)d_in[22];
    const float* wc_out   = (const float*)d_in[23];
    const float* bc_out   = (const float*)d_in[24];
    const float* wp_out   = (const float*)d_in[25];
    const float* bp_out   = (const float*)d_in[26];
    const float* we_out   = (const float*)d_in[27];
    const float* be_out   = (const float*)d_in[28];
    float* out = (float*)d_out;

    cudaFuncSetAttribute(fused_kernel,
                         cudaFuncAttributeMaxDynamicSharedMemorySize, SMEM_BYTES);

    prep_kernel<<<B_*N_, NTHR>>>(classes, params, wc_qkv, bc_qkv,
                                 wp_qkv, bp_qkv, we_out);
    fused_kernel<<<B_*N_, NTHR, SMEM_BYTES>>>(
        edges,
        fc_mul_w, fc_mul_b, fc_add_w, fc_add_b,
        fc_m1_w, fc_m1_b, fc_m2_w, fc_m2_b,
        fp_mul_w, fp_mul_b, fp_add_w, fp_add_b,
        fp_m1_w, fp_m1_b, fp_m2_w, fp_m2_b,
        wc_out, bc_out, wp_out, bp_out,
        be_out, out);
}

// round 3
// speedup vs baseline: 1.2965x; 1.2965x over previous
#include <cuda_runtime.h>
#include <cstdint>

using u64 = unsigned long long;
#define NTHR 256

constexpr int B_  = 2;
constexpr int N_  = 256;
constexpr int DC_ = 96;
constexpr int DP_ = 160;
constexpr int DE_ = 64;
constexpr int H_  = 8;
constexpr int KT  = 64;              // k rows per tile
constexpr int NT  = 4;               // tiles
constexpr int LDA = 264;             // bufA row stride (floats), padded

// ---------------- device scratch ----------------
__device__ float g_Qc[B_*N_*DC_];   // prescaled by 1/sqrt(96)
__device__ float g_Kc[B_*N_*DC_];
__device__ float g_Vc[B_*N_*DC_];
__device__ float g_Qp[B_*N_*DP_];   // prescaled by 1/sqrt(160)
__device__ float g_Kp[B_*N_*DP_];
__device__ float g_Vp[B_*N_*DP_];

// k-pair-interleaved packed weights: layout [K/2][N] of u64 {w[2k][c], w[2k+1][c]}
__device__ __align__(16) u64 gW1mul[32*256];   // cat [fc_mul | fp_mul], K=64
__device__ __align__(16) u64 gW1add[32*256];
__device__ __align__(16) u64 gWc1[48*96];
__device__ __align__(16) u64 gWc2[48*96];
__device__ __align__(16) u64 gWp1[80*160];
__device__ __align__(16) u64 gWp2[80*160];
__device__ __align__(16) u64 gWe[128*64];      // permuted we_out, K=256

// ---------------- shared layout (floats) ----------------
constexpr int OFF_QC  = 0;        // 96
constexpr int OFF_QP  = 96;       // 160
constexpr int OFF_WV  = 256;      // 256
constexpr int OFF_SCC = 512;      // 2048
constexpr int OFF_SCP = 2560;     // 2048
constexpr int OFF_MB  = 4608;     // 256  cat mul bias
constexpr int OFF_AB  = 4864;     // 256  cat add bias
constexpr int OFF_CB1 = 5120;     // 96
constexpr int OFF_CB2 = 5216;     // 96
constexpr int OFF_PB1 = 5312;     // 160
constexpr int OFF_PB2 = 5472;     // 160
constexpr int OFF_BE  = 5632;     // 64
constexpr int OFF_E   = 5696;     // 64*64 = 4096
constexpr int OFF_A   = 9792;     // 64*264 = 16896
constexpr int OFF_W   = 26688;    // 25600 (max stage)
constexpr int SMEM_FLOATS = 52288;
constexpr int SMEM_BYTES  = SMEM_FLOATS * 4;   // 209152

// ---------------- f32x2 helpers ----------------
__device__ __forceinline__ void fma2(u64& d, u64 a, u64 b) {
    asm("fma.rn.f32x2 %0, %1, %2, %0;" : "+l"(d) : "l"(a), "l"(b));
}
__device__ __forceinline__ float hsum2(u64 a) {
    float lo, hi;
    asm("mov.b64 {%0, %1}, %2;" : "=f"(lo), "=f"(hi) : "l"(a));
    return lo + hi;
}
__device__ __forceinline__ u64 pk2(float lo, float hi) {
    u64 r; asm("mov.b64 %0, {%1, %2};" : "=l"(r) : "f"(lo), "f"(hi)); return r;
}
__device__ __forceinline__ float lrelu(float v) { return v > 0.f ? v : 0.05f * v; }

// ============================= prep: QKV =============================
__global__ void __launch_bounds__(NTHR) prep_kernel(
    const float* __restrict__ classes, const float* __restrict__ params,
    const float* __restrict__ wc_qkv,  const float* __restrict__ bc_qkv,
    const float* __restrict__ wp_qkv,  const float* __restrict__ bp_qkv)
{
    __shared__ float rc[DC_];
    __shared__ float rp[DP_];
    const int bn = blockIdx.x;
    const int t  = threadIdx.x;
    if (t < DC_) rc[t] = classes[bn*DC_ + t];
    if (t < DP_) rp[t] = params[bn*DP_ + t];
    __syncthreads();

    const float invc = 0.10206207261596575f;   // 1/sqrt(96)
    const float invp = 0.07905694150420949f;   // 1/sqrt(160)

    for (int o = t; o < 3*DC_; o += NTHR) {
        float acc = bc_qkv[o];
        #pragma unroll 4
        for (int i = 0; i < DC_; i++) acc = fmaf(rc[i], wc_qkv[i*3*DC_ + o], acc);
        const int part = o / DC_, d = o - part*DC_;
        if (part == 0)      g_Qc[bn*DC_ + d] = acc * invc;
        else if (part == 1) g_Kc[bn*DC_ + d] = acc;
        else                g_Vc[bn*DC_ + d] = acc;
    }
    for (int o = t; o < 3*DP_; o += NTHR) {
        float acc = bp_qkv[o];
        #pragma unroll 4
        for (int i = 0; i < DP_; i++) acc = fmaf(rp[i], wp_qkv[i*3*DP_ + o], acc);
        const int part = o / DP_, d = o - part*DP_;
        if (part == 0)      g_Qp[bn*DP_ + d] = acc * invp;
        else if (part == 1) g_Kp[bn*DP_ + d] = acc;
        else                g_Vp[bn*DP_ + d] = acc;
    }
}

// ============================= prep: weight pack =============================
__global__ void __launch_bounds__(NTHR) pack_kernel(
    const float* __restrict__ fc_mul_w, const float* __restrict__ fc_add_w,
    const float* __restrict__ fc_m1_w,  const float* __restrict__ fc_m2_w,
    const float* __restrict__ fp_mul_w, const float* __restrict__ fp_add_w,
    const float* __restrict__ fp_m1_w,  const float* __restrict__ fp_m2_w,
    const float* __restrict__ we_out)
{
    const int i = blockIdx.x * NTHR + threadIdx.x;
    if (i < 16384) {                                   // W1mul / W1add (cat, K=64, N=256)
        const bool isAdd = i >= 8192;
        const int t = i & 8191, k2 = t >> 8, c = t & 255;
        const float* Wc = isAdd ? fc_add_w : fc_mul_w;
        const float* Wp = isAdd ? fp_add_w : fp_mul_w;
        float lo, hi;
        if (c < 96) { lo = Wc[(2*k2)*96 + c];      hi = Wc[(2*k2+1)*96 + c]; }
        else        { lo = Wp[(2*k2)*160 + c - 96]; hi = Wp[(2*k2+1)*160 + c - 96]; }
        (isAdd ? gW1add : gW1mul)[t] = pk2(lo, hi);
    } else if (i < 25600) {                            // class MLP (K=96, N=96)
        int t = i - 16384; const bool l2 = t >= 4608; if (l2) t -= 4608;
        const int k2 = t / 96, c = t % 96;
        const float* W = l2 ? fc_m2_w : fc_m1_w;
        (l2 ? gWc2 : gWc1)[t] = pk2(W[(2*k2)*96 + c], W[(2*k2+1)*96 + c]);
    } else if (i < 51200) {                            // param MLP (K=160, N=160)
        int t = i - 25600; const bool l2 = t >= 12800; if (l2) t -= 12800;
        const int k2 = t / 160, c = t % 160;
        const float* W = l2 ? fp_m2_w : fp_m1_w;
        (l2 ? gWp2 : gWp1)[t] = pk2(W[(2*k2)*160 + c], W[(2*k2+1)*160 + c]);
    } else if (i < 59392) {                            // permuted we_out (K=256, N=64)
        const int t = i - 51200, k2 = t / 64, c = t % 64;
        auto src = [] (int r) {
            return r < 96 ? (r/12)*32 + (r%12) : ((r-96)/20)*32 + 12 + ((r-96)%20);
        };
        gWe[t] = pk2(we_out[src(2*k2)*64 + c], we_out[src(2*k2+1)*64 + c]);
    }
}

// ============================= packed-pair GEMM =============================
// acc[R][J]: lane accumulates even/odd-k partials for scalar cols cb + 32*j.
// A0: activation row base (stride ldaf floats, even). Wp: [K/2][Ncols] u64.
template<int R, int J, int KD>
__device__ __forceinline__ void pgemm(const float* A0, int ldaf,
                                      const u64* Wp, int Ncols, int cb,
                                      u64 acc[R][J])
{
    const u64* a2[R];
    #pragma unroll
    for (int r = 0; r < R; r++) a2[r] = reinterpret_cast<const u64*>(A0 + r*ldaf);
    const u64* wp = Wp + cb;
    #pragma unroll
    for (int r = 0; r < R; r++)
        #pragma unroll
        for (int j = 0; j < J; j++) acc[r][j] = 0ull;
    constexpr int K2 = KD / 2;
    #pragma unroll 4
    for (int k2 = 0; k2 < K2; k2++) {
        u64 w[J];
        #pragma unroll
        for (int j = 0; j < J; j++) w[j] = wp[k2*Ncols + 32*j];
        #pragma unroll
        for (int r = 0; r < R; r++) {
            const u64 av = a2[r][k2];
            #pragma unroll
            for (int j = 0; j < J; j++) fma2(acc[r][j], av, w[j]);
        }
    }
}

__device__ __forceinline__ void stage_cp(float* dst, const float* src, int n, int tid)
{
    float4* d4 = reinterpret_cast<float4*>(dst);
    const float4* s4 = reinterpret_cast<const float4*>(src);
    const int n4 = n >> 2;
    for (int i = tid; i < n4; i += NTHR) d4[i] = s4[i];
}

// ============================= fused main kernel =============================
__global__ void __launch_bounds__(NTHR, 1) fused_kernel(
    const float* __restrict__ edges,
    const float* __restrict__ fc_mul_b, const float* __restrict__ fc_add_b,
    const float* __restrict__ fc_m1_b,  const float* __restrict__ fc_m2_b,
    const float* __restrict__ fp_mul_b, const float* __restrict__ fp_add_b,
    const float* __restrict__ fp_m1_b,  const float* __restrict__ fp_m2_b,
    const float* __restrict__ wc_out,   const float* __restrict__ bc_out,
    const float* __restrict__ wp_out,   const float* __restrict__ bp_out,
    const float* __restrict__ be_out,
    float* __restrict__ out)
{
    extern __shared__ float sm[];
    float* sQc  = sm + OFF_QC;
    float* sQp  = sm + OFF_QP;
    float* sWV  = sm + OFF_WV;
    float* sScC = sm + OFF_SCC;
    float* sScP = sm + OFF_SCP;
    float* sMB  = sm + OFF_MB;
    float* sAB  = sm + OFF_AB;
    float* sCB1 = sm + OFF_CB1;
    float* sCB2 = sm + OFF_CB2;
    float* sPB1 = sm + OFF_PB1;
    float* sPB2 = sm + OFF_PB2;
    float* sBE  = sm + OFF_BE;
    float* sE   = sm + OFF_E;
    float* bufA = sm + OFF_A;
    float* sW   = sm + OFF_W;

    const int tid  = threadIdx.x;
    const int warp = tid >> 5;
    const int lane = tid & 31;
    const int bq   = blockIdx.x;
    const int b    = bq >> 8;
    const int r0   = warp * 8;       // this warp's 8 rows within the tile

    // persistent stages: Q rows + all biases
    for (int i = tid; i < DC_; i += NTHR) {
        sQc[i]  = g_Qc[bq*DC_ + i];
        sMB[i]  = fc_mul_b[i];  sAB[i]  = fc_add_b[i];
        sCB1[i] = fc_m1_b[i];   sCB2[i] = fc_m2_b[i];
    }
    for (int i = tid; i < DP_; i += NTHR) {
        sQp[i]      = g_Qp[bq*DP_ + i];
        sMB[96+i]   = fp_mul_b[i];  sAB[96+i] = fp_add_b[i];
        sPB1[i]     = fp_m1_b[i];   sPB2[i]   = fp_m2_b[i];
    }
    if (tid < DE_) sBE[tid] = be_out[tid];

    const float* Eb  = edges + (size_t)bq * N_ * DE_;
    float* outE = out + (size_t)(B_*N_*DC_ + B_*N_*DP_) + (size_t)bq * N_ * DE_;

    for (int t = 0; t < NT; t++) {
        const int k0 = t * KT;
        __syncthreads();
        // ---- stage E tile + cat mul weights ----
        {
            const float4* src = reinterpret_cast<const float4*>(Eb + (size_t)k0 * DE_);
            float4* dst = reinterpret_cast<float4*>(sE);
            for (int i = tid; i < KT*DE_/4; i += NTHR) dst[i] = src[i];
        }
        stage_cp(sW, (const float*)gW1mul, 32*256*2, tid);
        __syncthreads();
        // ---- pass m: m = E @ Wmul_cat + mb  (store to bufA) ----
        #pragma unroll
        for (int jh = 0; jh < 2; jh++) {
            u64 acc[8][4];
            pgemm<8,4,64>(sE + r0*DE_, DE_, (const u64*)sW, 256, jh*128 + lane, acc);
            #pragma unroll
            for (int i = 0; i < 8; i++) {
                const int r = r0 + i;
                #pragma unroll
                for (int j = 0; j < 4; j++) {
                    const int c = jh*128 + lane + 32*j;
                    bufA[r*LDA + c] = hsum2(acc[i][j]) + sMB[c];
                }
            }
        }
        __syncthreads();
        stage_cp(sW, (const float*)gW1add, 32*256*2, tid);
        __syncthreads();
        // ---- pass x: x = a*m + (E@Wadd + ab) + a,  a = Q⊙K/sqrt(d) ----
        #pragma unroll
        for (int jh = 0; jh < 2; jh++) {
            u64 acc[8][4];
            pgemm<8,4,64>(sE + r0*DE_, DE_, (const u64*)sW, 256, jh*128 + lane, acc);
            #pragma unroll
            for (int i = 0; i < 8; i++) {
                const int r = r0 + i, k = k0 + r;
                const float* KcR = g_Kc + (size_t)(b*N_ + k) * DC_;
                const float* KpR = g_Kp + (size_t)(b*N_ + k) * DP_;
                #pragma unroll
                for (int j = 0; j < 4; j++) {
                    const int c = jh*128 + lane + 32*j;
                    const float addv = hsum2(acc[i][j]) + sAB[c];
                    float a;
                    if (jh == 0 && j < 3) a = sQc[c] * KcR[c];
                    else { const int p = c - 96; a = sQp[p] * KpR[p]; }
                    const float m = bufA[r*LDA + c];
                    bufA[r*LDA + c] = fmaf(a, m, addv + a);
                }
            }
        }
        // ---- class MLP layer 1 (in-place, warp-private rows) ----
        __syncthreads();
        stage_cp(sW, (const float*)gWc1, 48*96*2, tid);
        __syncthreads();
        {
            u64 acc[8][3];
            pgemm<8,3,96>(bufA + r0*LDA, LDA, (const u64*)sW, 96, lane, acc);
            #pragma unroll
            for (int i = 0; i < 8; i++)
                #pragma unroll
                for (int j = 0; j < 3; j++) {
                    const int c = lane + 32*j;
                    bufA[(r0+i)*LDA + c] = lrelu(hsum2(acc[i][j]) + sCB1[c]);
                }
        }
        // ---- param MLP layer 1 ----
        __syncthreads();
        stage_cp(sW, (const float*)gWp1, 80*160*2, tid);
        __syncthreads();
        {
            u64 acc[8][5];
            pgemm<8,5,160>(bufA + r0*LDA + 96, LDA, (const u64*)sW, 160, lane, acc);
            #pragma unroll
            for (int i = 0; i < 8; i++)
                #pragma unroll
                for (int j = 0; j < 5; j++) {
                    const int c = lane + 32*j;
                    bufA[(r0+i)*LDA + 96 + c] = lrelu(hsum2(acc[i][j]) + sPB1[c]);
                }
        }
        // ---- class MLP layer 2 ----
        __syncthreads();
        stage_cp(sW, (const float*)gWc2, 48*96*2, tid);
        __syncthreads();
        {
            u64 acc[8][3];
            pgemm<8,3,96>(bufA + r0*LDA, LDA, (const u64*)sW, 96, lane, acc);
            #pragma unroll
            for (int i = 0; i < 8; i++)
                #pragma unroll
                for (int j = 0; j < 3; j++) {
                    const int c = lane + 32*j;
                    bufA[(r0+i)*LDA + c] = lrelu(hsum2(acc[i][j]) + sCB2[c]);
                }
        }
        // ---- param MLP layer 2 ----
        __syncthreads();
        stage_cp(sW, (const float*)gWp2, 80*160*2, tid);
        __syncthreads();
        {
            u64 acc[8][5];
            pgemm<8,5,160>(bufA + r0*LDA + 96, LDA, (const u64*)sW, 160, lane, acc);
            #pragma unroll
            for (int i = 0; i < 8; i++)
                #pragma unroll
                for (int j = 0; j < 5; j++) {
                    const int c = lane + 32*j;
                    bufA[(r0+i)*LDA + 96 + c] = lrelu(hsum2(acc[i][j]) + sPB2[c]);
                }
        }
        // ---- per-head score sums + stage permuted we_out ----
        __syncthreads();
        for (int tau = tid; tau < KT*16; tau += NTHR) {
            const int r = tau >> 4;
            const int rest = tau & 15;
            const int h = rest >> 1;
            if ((rest & 1) == 0) {
                const float* p = bufA + r*LDA + h*12;
                float s = 0.f;
                #pragma unroll
                for (int d = 0; d < 12; d++) s += p[d];
                sScC[(k0 + r)*H_ + h] = s;
            } else {
                const float* p = bufA + r*LDA + 96 + h*20;
                float s = 0.f;
                #pragma unroll
                for (int d = 0; d < 20; d++) s += p[d];
                sScP[(k0 + r)*H_ + h] = s;
            }
        }
        stage_cp(sW, (const float*)gWe, 128*64*2, tid);
        __syncthreads();
        // ---- out_e = y2_cat(permuted) @ we_out + be ----
        {
            u64 acc[8][2];
            pgemm<8,2,256>(bufA + r0*LDA, LDA, (const u64*)sW, 64, lane, acc);
            #pragma unroll
            for (int i = 0; i < 8; i++) {
                const int k = k0 + r0 + i;
                float* op = outE + (size_t)k * DE_;
                #pragma unroll
                for (int j = 0; j < 2; j++) {
                    const int c = lane + 32*j;
                    op[c] = hsum2(acc[i][j]) + sBE[c];
                }
            }
        }
    }
    __syncthreads();

    // ---- softmax over k per head (warp h owns head h) ----
    {
        const int h = warp;
        #pragma unroll
        for (int ty = 0; ty < 2; ty++) {
            float* S = ty ? sScP : sScC;
            float m = -1e30f;
            for (int k = lane; k < N_; k += 32) m = fmaxf(m, S[k*H_ + h]);
            #pragma unroll
            for (int o = 16; o; o >>= 1) m = fmaxf(m, __shfl_xor_sync(0xffffffffu, m, o));
            float sum = 0.f;
            for (int k = lane; k < N_; k += 32) {
                const float e = __expf(S[k*H_ + h] - m);
                S[k*H_ + h] = e;
                sum += e;
            }
            #pragma unroll
            for (int o = 16; o; o >>= 1) sum += __shfl_xor_sync(0xffffffffu, sum, o);
            const float inv = 1.f / sum;
            for (int k = lane; k < N_; k += 32) S[k*H_ + h] *= inv;
        }
    }
    __syncthreads();

    // ---- weighted V (cross: ap weights Vc, ac weights Vp) ----
    {
        float acc = 0.f;
        if (tid < DC_) {
            const int c = tid, h = c / 12;
            const float* V = g_Vc + (size_t)(b*N_) * DC_ + c;
            for (int k = 0; k < N_; k++) acc = fmaf(sScP[k*H_ + h], V[(size_t)k*DC_], acc);
        } else {
            const int p = tid - DC_, h = p / 20;
            const float* V = g_Vp + (size_t)(b*N_) * DP_ + p;
            for (int k = 0; k < N_; k++) acc = fmaf(sScC[k*H_ + h], V[(size_t)k*DP_], acc);
        }
        sWV[tid] = acc;
    }
    __syncthreads();

    // ---- output projections ----
    if (tid < DC_) {
        const int o = tid;
        float acc = bc_out[o];
        for (int c = 0; c < DC_; c++) acc = fmaf(sWV[c], wc_out[c*DC_ + o], acc);
        out[(size_t)bq*DC_ + o] = acc;
    } else {
        const int o = tid - DC_;
        float acc = bp_out[o];
        for (int p = 0; p < DP_; p++) acc = fmaf(sWV[DC_ + p], wp_out[p*DP_ + o], acc);
        out[(size_t)(B_*N_*DC_) + (size_t)bq*DP_ + o] = acc;
    }
}

// ============================= launch =============================
extern "C" void kernel_launch(void* const* d_in, const int* in_sizes, int n_in,
                              void* d_out, int out_size)
{
    const float* classes  = (const float*)d_in[0];
    const float* params   = (const float*)d_in[1];
    const float* edges    = (const float*)d_in[2];
    const float* wc_qkv   = (const float*)d_in[3];
    const float* bc_qkv   = (const float*)d_in[4];
    const float* wp_qkv   = (const float*)d_in[5];
    const float* bp_qkv   = (const float*)d_in[6];
    const float* fc_mul_w = (const float*)d_in[7];
    const float* fc_mul_b = (const float*)d_in[8];
    const float* fc_add_w = (const float*)d_in[9];
    const float* fc_add_b = (const float*)d_in[10];
    const float* fc_m1_w  = (const float*)d_in[11];
    const float* fc_m1_b  = (const float*)d_in[12];
    const float* fc_m2_w  = (const float*)d_in[13];
    const float* fc_m2_b  = (const float*)d_in[14];
    const float* fp_mul_w = (const float*)d_in[15];
    const float* fp_mul_b = (const float*)d_in[16];
    const float* fp_add_w = (const float*)d_in[17];
    const float* fp_add_b = (const float*)d_in[18];
    const float* fp_m1_w  = (const float*)d_in[19];
    const float* fp_m1_b  = (const float*)d_in[20];
    const float* fp_m2_w  = (const float*)d_in[21];
    const float* fp_m2_b  = (const float*)d_in[22];
    const float* wc_out   = (const float*)d_in[23];
    const float* bc_out   = (const float*)d_in[24];
    const float* wp_out   = (const float*)d_in[25];
    const float* bp_out   = (const float*)d_in[26];
    const float* we_out   = (const float*)d_in[27];
    const float* be_out   = (const float*)d_in[28];
    float* out = (float*)d_out;

    cudaFuncSetAttribute(fused_kernel,
                         cudaFuncAttributeMaxDynamicSharedMemorySize, SMEM_BYTES);

    pack_kernel<<<(59392 + NTHR - 1)/NTHR, NTHR>>>(
        fc_mul_w, fc_add_w, fc_m1_w, fc_m2_w,
        fp_mul_w, fp_add_w, fp_m1_w, fp_m2_w, we_out);
    prep_kernel<<<B_*N_, NTHR>>>(classes, params, wc_qkv, bc_qkv, wp_qkv, bp_qkv);
    fused_kernel<<<B_*N_, NTHR, SMEM_BYTES>>>(
        edges,
        fc_mul_b, fc_add_b, fc_m1_b, fc_m2_b,
        fp_mul_b, fp_add_b, fp_m1_b, fp_m2_b,
        wc_out, bc_out, wp_out, bp_out,
        be_out, out);
}

// round 7
// speedup vs baseline: 1.6476x; 1.2708x over previous
#include <cuda_runtime.h>
#include <cuda_bf16.h>
#include <cstdint>

#define NTHR 256
using ushort_t = unsigned short;

constexpr int B_  = 2;
constexpr int N_  = 256;
constexpr int DC_ = 96;
constexpr int DP_ = 160;
constexpr int DE_ = 64;
constexpr int H_  = 8;
constexpr int KT  = 64;        // k rows per tile
constexpr int NT_ = 4;         // tiles
constexpr int LDE = 72;        // bf16 elems; /2=36 ≡ 4 mod 32 -> conflict-free
constexpr int LDX = 264;       // /2=132 ≡ 4 mod 32
constexpr int LDY = 200;       // /2=100 ≡ 4 mod 32
constexpr int LDW = 72;        // weight chunk row: 32k * (hi|lo) = 64 + pad 8

// ---------------- device scratch (fp32) ----------------
__device__ float g_Qcat[B_*N_*256];   // [Qc*inv_sqrt96 | Qp*inv_sqrt160]
__device__ float g_Kcat[B_*N_*256];   // [Kc | Kp]
__device__ float g_Vc[B_*N_*DC_];
__device__ float g_Vp[B_*N_*DP_];

// ---------------- split-bf16 weights, chunked along K (32 per chunk) ----------
// layout: chunk*(N*72) + n*72 + ktile*32 + kk   (hi), +16 (lo); ktile = (k%32)/16
__device__ __align__(16) ushort_t gW1mul[2*256*72];   // K=64, N=256 (cat)
__device__ __align__(16) ushort_t gW1add[2*256*72];
__device__ __align__(16) ushort_t gWc1[3*96*72];      // K=96, N=96
__device__ __align__(16) ushort_t gWc2[3*96*72];
__device__ __align__(16) ushort_t gWp1[5*160*72];     // K=160, N=160
__device__ __align__(16) ushort_t gWp2[5*160*72];
__device__ __align__(16) ushort_t gWe[8*64*72];       // K=256 (permuted), N=64

// ---------------- shared memory byte offsets ----------------
constexpr int OFFB_Q   = 0;        // 256 f
constexpr int OFFB_WV  = 1024;     // 256 f
constexpr int OFFB_SCC = 2048;     // 2048 f
constexpr int OFFB_SCP = 10240;    // 2048 f
constexpr int OFFB_MB  = 18432;    // 256 f
constexpr int OFFB_AB  = 19456;    // 256 f
constexpr int OFFB_CB1 = 20480;    // 96 f
constexpr int OFFB_CB2 = 20864;
constexpr int OFFB_PB1 = 21248;    // 160 f
constexpr int OFFB_PB2 = 21888;
constexpr int OFFB_BE  = 22528;    // 64 f
constexpr int OFFB_EHI = 22784;    // 64*72 bf16 = 9216 B
constexpr int OFFB_ELO = 32000;
constexpr int OFFB_XHI = 41216;    // 64*264 bf16 = 33792 B
constexpr int OFFB_XLO = 75008;
constexpr int OFFB_YHI = 108800;   // 64*200 bf16 = 25600 B
constexpr int OFFB_YLO = 134400;
constexpr int OFFB_WS  = 160000;   // 256*72 bf16 = 36864 B
constexpr int SMEM_BYTES = 196864;

// ---------------- helpers ----------------
__device__ __forceinline__ float bf2f(ushort_t u) {
    return __uint_as_float(((unsigned)u) << 16);
}
__device__ __forceinline__ void split2(float x0, float x1, unsigned& hi, unsigned& lo) {
    const ushort_t h0 = __bfloat16_as_ushort(__float2bfloat16_rn(x0));
    const ushort_t h1 = __bfloat16_as_ushort(__float2bfloat16_rn(x1));
    const ushort_t l0 = __bfloat16_as_ushort(__float2bfloat16_rn(x0 - bf2f(h0)));
    const ushort_t l1 = __bfloat16_as_ushort(__float2bfloat16_rn(x1 - bf2f(h1)));
    hi = (unsigned)h0 | ((unsigned)h1 << 16);
    lo = (unsigned)l0 | ((unsigned)l1 << 16);
}
__device__ __forceinline__ void mma_bf16(float (&d)[4], const unsigned (&a)[4],
                                         const unsigned (&b)[2]) {
    asm("mma.sync.aligned.m16n8k16.row.col.f32.bf16.bf16.f32 "
        "{%0,%1,%2,%3},{%4,%5,%6,%7},{%8,%9},{%0,%1,%2,%3};"
        : "+f"(d[0]), "+f"(d[1]), "+f"(d[2]), "+f"(d[3])
        : "r"(a[0]), "r"(a[1]), "r"(a[2]), "r"(a[3]), "r"(b[0]), "r"(b[1]));
}
__device__ __forceinline__ float lrelu(float v) { return v > 0.f ? v : 0.05f * v; }

// weight chunk address (hi element; lo at +16)
__host__ __device__ __forceinline__ int waddr(int k, int n, int N) {
    return (k >> 5) * (N * 72) + n * 72 + (((k & 31) >> 4) << 5) + (k & 15);
}

// ============================= prep: QKV =============================
__global__ void __launch_bounds__(NTHR) prep_kernel(
    const float* __restrict__ classes, const float* __restrict__ params,
    const float* __restrict__ wc_qkv,  const float* __restrict__ bc_qkv,
    const float* __restrict__ wp_qkv,  const float* __restrict__ bp_qkv)
{
    __shared__ float rc[DC_];
    __shared__ float rp[DP_];
    const int bn = blockIdx.x;
    const int t  = threadIdx.x;
    if (t < DC_) rc[t] = classes[bn*DC_ + t];
    if (t < DP_) rp[t] = params[bn*DP_ + t];
    __syncthreads();

    const float invc = 0.10206207261596575f;   // 1/sqrt(96)
    const float invp = 0.07905694150420949f;   // 1/sqrt(160)

    for (int o = t; o < 3*DC_; o += NTHR) {
        float acc = bc_qkv[o];
        #pragma unroll 4
        for (int i = 0; i < DC_; i++) acc = fmaf(rc[i], wc_qkv[i*3*DC_ + o], acc);
        const int part = o / DC_, d = o - part*DC_;
        if (part == 0)      g_Qcat[bn*256 + d] = acc * invc;
        else if (part == 1) g_Kcat[bn*256 + d] = acc;
        else                g_Vc[bn*DC_ + d] = acc;
    }
    for (int o = t; o < 3*DP_; o += NTHR) {
        float acc = bp_qkv[o];
        #pragma unroll 4
        for (int i = 0; i < DP_; i++) acc = fmaf(rp[i], wp_qkv[i*3*DP_ + o], acc);
        const int part = o / DP_, d = o - part*DP_;
        if (part == 0)      g_Qcat[bn*256 + 96 + d] = acc * invp;
        else if (part == 1) g_Kcat[bn*256 + 96 + d] = acc;
        else                g_Vp[bn*DP_ + d] = acc;
    }
}

// ============================= prep: weight split/pack =============================
__global__ void __launch_bounds__(NTHR) pack_kernel(
    const float* __restrict__ fc_mul_w, const float* __restrict__ fc_add_w,
    const float* __restrict__ fc_m1_w,  const float* __restrict__ fc_m2_w,
    const float* __restrict__ fp_mul_w, const float* __restrict__ fp_add_w,
    const float* __restrict__ fp_m1_w,  const float* __restrict__ fp_m2_w,
    const float* __restrict__ we_out)
{
    int i = blockIdx.x * NTHR + threadIdx.x;
    float v; ushort_t* dst; int addr;
    if (i < 32768) {                                   // W1 mul/add, K=64 N=256
        const bool isAdd = i >= 16384;
        const int t = i & 16383, k = t >> 8, n = t & 255;
        if (n < 96) v = (isAdd ? fc_add_w : fc_mul_w)[k*96 + n];
        else        v = (isAdd ? fp_add_w : fp_mul_w)[k*160 + n - 96];
        dst = isAdd ? gW1add : gW1mul; addr = waddr(k, n, 256);
    } else if ((i -= 32768) < 18432) {                 // Wc m1/m2, K=96 N=96
        const bool l2 = i >= 9216;
        const int t = l2 ? i - 9216 : i, k = t / 96, n = t % 96;
        v = (l2 ? fc_m2_w : fc_m1_w)[k*96 + n];
        dst = l2 ? gWc2 : gWc1; addr = waddr(k, n, 96);
    } else if ((i -= 18432) < 51200) {                 // Wp m1/m2, K=160 N=160
        const bool l2 = i >= 25600;
        const int t = l2 ? i - 25600 : i, k = t / 160, n = t % 160;
        v = (l2 ? fp_m2_w : fp_m1_w)[k*160 + n];
        dst = l2 ? gWp2 : gWp1; addr = waddr(k, n, 160);
    } else if ((i -= 51200) < 16384) {                 // We, K=256 (permuted) N=64
        const int k = i >> 6, n = i & 63;
        const int src = k < 96 ? (k/12)*32 + (k%12)
                               : ((k-96)/20)*32 + 12 + ((k-96)%20);
        v = we_out[src*64 + n];
        dst = gWe; addr = waddr(k, n, 64);
    } else return;
    const ushort_t h = __bfloat16_as_ushort(__float2bfloat16_rn(v));
    const ushort_t l = __bfloat16_as_ushort(__float2bfloat16_rn(v - bf2f(h)));
    dst[addr]      = h;
    dst[addr + 16] = l;
}

// ---------------- A fragment load (row-major bf16) ----------------
__device__ __forceinline__ void ldA(unsigned (&A)[4], const ushort_t* base,
                                    int lda, int row, int col) {
    const ushort_t* p = base + row*lda + col;
    A[0] = *reinterpret_cast<const unsigned*>(p);
    A[1] = *reinterpret_cast<const unsigned*>(p + 8*lda);
    A[2] = *reinterpret_cast<const unsigned*>(p + 8);
    A[3] = *reinterpret_cast<const unsigned*>(p + 8*lda + 8);
}

// ---------------- one K=32 chunk, 3-product split mma ----------------
template<int NTILES>
__device__ __forceinline__ void mma_chunk(
    const ushort_t* __restrict__ Ahi, const ushort_t* __restrict__ Alo,
    int lda, int aoff,
    const ushort_t* __restrict__ W, int nb,
    float (&acc)[2][NTILES][4], int lane, int mg)
{
    const int g = lane >> 2, t = lane & 3;
    #pragma unroll
    for (int kt = 0; kt < 2; kt++) {
        unsigned Ah[2][4], Al[2][4];
        #pragma unroll
        for (int mt = 0; mt < 2; mt++) {
            const int row = mg*32 + mt*16 + g;
            const int col = aoff + kt*16 + 2*t;
            ldA(Ah[mt], Ahi, lda, row, col);
            ldA(Al[mt], Alo, lda, row, col);
        }
        #pragma unroll
        for (int nt = 0; nt < NTILES; nt++) {
            const ushort_t* wp = W + (nb + nt*8 + g)*LDW + kt*32 + 2*t;
            unsigned Bh[2], Bl[2];
            Bh[0] = *reinterpret_cast<const unsigned*>(wp);
            Bh[1] = *reinterpret_cast<const unsigned*>(wp + 8);
            Bl[0] = *reinterpret_cast<const unsigned*>(wp + 16);
            Bl[1] = *reinterpret_cast<const unsigned*>(wp + 24);
            #pragma unroll
            for (int mt = 0; mt < 2; mt++) {
                mma_bf16(acc[mt][nt], Ah[mt], Bh);
                mma_bf16(acc[mt][nt], Ah[mt], Bl);
                mma_bf16(acc[mt][nt], Al[mt], Bh);
            }
        }
    }
}

// ---------------- chunked GEMM driver (stages weights, runs mma) ----------------
template<int NTILES, int NCH>
__device__ __forceinline__ void gemm_run(
    const ushort_t* __restrict__ gW, int Nrows,
    const ushort_t* __restrict__ Ahi, const ushort_t* __restrict__ Alo,
    int lda, int abase,
    ushort_t* sWS, int nb, float (&acc)[2][NTILES][4],
    int tid, int lane, int mg)
{
    #pragma unroll 1
    for (int ch = 0; ch < NCH; ch++) {
        __syncthreads();
        const uint4* src = reinterpret_cast<const uint4*>(gW + ch*Nrows*LDW);
        uint4* dst = reinterpret_cast<uint4*>(sWS);
        const int n16 = Nrows * 9;   // LDW*2B/16B = 9 uint4 per row
        for (int i = tid; i < n16; i += NTHR) dst[i] = src[i];
        __syncthreads();
        mma_chunk<NTILES>(Ahi, Alo, lda, abase + ch*32, sWS, nb, acc, lane, mg);
    }
}

// ---------------- MLP epilogue: lrelu(acc + bias) -> split store ----------------
template<int NTILES>
__device__ __forceinline__ void mlp_epi(
    float (&acc)[2][NTILES][4], const float* __restrict__ bias, int nbase,
    ushort_t* __restrict__ Dhi, ushort_t* __restrict__ Dlo, int ldd, int coff,
    int lane, int mg)
{
    const int g = lane >> 2, t = lane & 3;
    #pragma unroll
    for (int mt = 0; mt < 2; mt++) {
        const int rb = mg*32 + mt*16 + g;
        #pragma unroll
        for (int nt = 0; nt < NTILES; nt++) {
            const int c = nbase + nt*8 + 2*t;
            const float b0 = bias[c], b1 = bias[c+1];
            unsigned h, l;
            split2(lrelu(acc[mt][nt][0] + b0), lrelu(acc[mt][nt][1] + b1), h, l);
            *reinterpret_cast<unsigned*>(&Dhi[rb*ldd + coff + c]) = h;
            *reinterpret_cast<unsigned*>(&Dlo[rb*ldd + coff + c]) = l;
            split2(lrelu(acc[mt][nt][2] + b0), lrelu(acc[mt][nt][3] + b1), h, l);
            *reinterpret_cast<unsigned*>(&Dhi[(rb+8)*ldd + coff + c]) = h;
            *reinterpret_cast<unsigned*>(&Dlo[(rb+8)*ldd + coff + c]) = l;
        }
    }
}

// ============================= fused main kernel =============================
__global__ void __launch_bounds__(NTHR, 1) fused_kernel(
    const float* __restrict__ edges,
    const float* __restrict__ fc_mul_b, const float* __restrict__ fc_add_b,
    const float* __restrict__ fc_m1_b,  const float* __restrict__ fc_m2_b,
    const float* __restrict__ fp_mul_b, const float* __restrict__ fp_add_b,
    const float* __restrict__ fp_m1_b,  const float* __restrict__ fp_m2_b,
    const float* __restrict__ wc_out,   const float* __restrict__ bc_out,
    const float* __restrict__ wp_out,   const float* __restrict__ bp_out,
    const float* __restrict__ be_out,
    float* __restrict__ out)
{
    extern __shared__ char smc[];
    float* sQ   = reinterpret_cast<float*>(smc + OFFB_Q);
    float* sWV  = reinterpret_cast<float*>(smc + OFFB_WV);
    float* sScC = reinterpret_cast<float*>(smc + OFFB_SCC);
    float* sScP = reinterpret_cast<float*>(smc + OFFB_SCP);
    float* sMB  = reinterpret_cast<float*>(smc + OFFB_MB);
    float* sAB  = reinterpret_cast<float*>(smc + OFFB_AB);
    float* sCB1 = reinterpret_cast<float*>(smc + OFFB_CB1);
    float* sCB2 = reinterpret_cast<float*>(smc + OFFB_CB2);
    float* sPB1 = reinterpret_cast<float*>(smc + OFFB_PB1);
    float* sPB2 = reinterpret_cast<float*>(smc + OFFB_PB2);
    float* sBE  = reinterpret_cast<float*>(smc + OFFB_BE);
    ushort_t* sEhi = reinterpret_cast<ushort_t*>(smc + OFFB_EHI);
    ushort_t* sElo = reinterpret_cast<ushort_t*>(smc + OFFB_ELO);
    ushort_t* sXhi = reinterpret_cast<ushort_t*>(smc + OFFB_XHI);
    ushort_t* sXlo = reinterpret_cast<ushort_t*>(smc + OFFB_XLO);
    ushort_t* sYhi = reinterpret_cast<ushort_t*>(smc + OFFB_YHI);
    ushort_t* sYlo = reinterpret_cast<ushort_t*>(smc + OFFB_YLO);
    ushort_t* sWS  = reinterpret_cast<ushort_t*>(smc + OFFB_WS);

    const int tid  = threadIdx.x;
    const int warp = tid >> 5;
    const int lane = tid & 31;
    const int mg   = warp >> 2;      // 0..1 row group (32 rows)
    const int ng   = warp & 3;       // 0..3 col group
    const int g    = lane >> 2, t4 = lane & 3;
    const int bq   = blockIdx.x;
    const int b    = bq >> 8;

    // persistent stages
    for (int i = tid; i < 256; i += NTHR) sQ[i] = g_Qcat[bq*256 + i];
    for (int i = tid; i < DC_; i += NTHR) {
        sMB[i]  = fc_mul_b[i];  sAB[i]  = fc_add_b[i];
        sCB1[i] = fc_m1_b[i];   sCB2[i] = fc_m2_b[i];
    }
    for (int i = tid; i < DP_; i += NTHR) {
        sMB[96+i] = fp_mul_b[i];  sAB[96+i] = fp_add_b[i];
        sPB1[i]   = fp_m1_b[i];   sPB2[i]   = fp_m2_b[i];
    }
    if (tid < DE_) sBE[tid] = be_out[tid];

    const float* Eb = edges + (size_t)bq * N_ * DE_;
    float* outE = out + (size_t)(B_*N_*DC_ + B_*N_*DP_) + (size_t)bq * N_ * DE_;

    for (int tt = 0; tt < NT_; tt++) {
        const int k0 = tt * KT;
        __syncthreads();
        // ---- load + split E tile ----
        for (int idx = tid; idx < KT*32; idx += NTHR) {
            const int r = idx >> 5, kp = (idx & 31) * 2;
            const float2 e2 = *reinterpret_cast<const float2*>(
                &Eb[(size_t)(k0 + r)*DE_ + kp]);
            unsigned h, l; split2(e2.x, e2.y, h, l);
            *reinterpret_cast<unsigned*>(&sEhi[r*LDE + kp]) = h;
            *reinterpret_cast<unsigned*>(&sElo[r*LDE + kp]) = l;
        }
        // ========== stage 1 pass A: m = E @ Wmul + mb  -> split-store to X ====
        {
            float acc[2][8][4] = {};
            gemm_run<8,2>(gW1mul, 256, sEhi, sElo, LDE, 0, sWS, ng*64, acc,
                          tid, lane, mg);
            #pragma unroll
            for (int mt = 0; mt < 2; mt++) {
                const int rb = mg*32 + mt*16 + g;
                #pragma unroll
                for (int nt = 0; nt < 8; nt++) {
                    const int c = ng*64 + nt*8 + 2*t4;
                    const float mb0 = sMB[c], mb1 = sMB[c+1];
                    #pragma unroll
                    for (int hh = 0; hh < 2; hh++) {
                        const int r = rb + hh*8;
                        unsigned h, l;
                        split2(acc[mt][nt][2*hh+0] + mb0,
                               acc[mt][nt][2*hh+1] + mb1, h, l);
                        *reinterpret_cast<unsigned*>(&sXhi[r*LDX + c]) = h;
                        *reinterpret_cast<unsigned*>(&sXlo[r*LDX + c]) = l;
                    }
                }
            }
        }
        // ========== stage 1 pass B: add-GEMM + FiLM epilogue (reads m from X) ==
        {
            float acc[2][8][4] = {};
            gemm_run<8,2>(gW1add, 256, sEhi, sElo, LDE, 0, sWS, ng*64, acc,
                          tid, lane, mg);
            #pragma unroll
            for (int mt = 0; mt < 2; mt++) {
                const int rb = mg*32 + mt*16 + g;
                #pragma unroll
                for (int nt = 0; nt < 8; nt++) {
                    const int c = ng*64 + nt*8 + 2*t4;
                    const float q0 = sQ[c], q1 = sQ[c+1];
                    const float ab0 = sAB[c], ab1 = sAB[c+1];
                    #pragma unroll
                    for (int hh = 0; hh < 2; hh++) {
                        const int r = rb + hh*8;
                        // reconstruct m (same thread wrote it in pass A)
                        const float m0 = bf2f(sXhi[r*LDX + c])
                                       + bf2f(sXlo[r*LDX + c]);
                        const float m1 = bf2f(sXhi[r*LDX + c + 1])
                                       + bf2f(sXlo[r*LDX + c + 1]);
                        const float2 kv = *reinterpret_cast<const float2*>(
                            &g_Kcat[(size_t)(b*N_ + k0 + r)*256 + c]);
                        const float a0 = q0 * kv.x, a1 = q1 * kv.y;
                        const float x0 = fmaf(a0, m0, acc[mt][nt][2*hh+0] + ab0 + a0);
                        const float x1 = fmaf(a1, m1, acc[mt][nt][2*hh+1] + ab1 + a1);
                        unsigned h, l; split2(x0, x1, h, l);
                        *reinterpret_cast<unsigned*>(&sXhi[r*LDX + c]) = h;
                        *reinterpret_cast<unsigned*>(&sXlo[r*LDX + c]) = l;
                    }
                }
            }
        }
        // ================= class MLP layer 1 (X[0:96] -> Y[0:96]) ============
        {
            float acc[2][3][4] = {};
            gemm_run<3,3>(gWc1, 96, sXhi, sXlo, LDX, 0, sWS, ng*24, acc, tid, lane, mg);
            mlp_epi<3>(acc, sCB1, ng*24, sYhi, sYlo, LDY, 0, lane, mg);
        }
        // ================= class MLP layer 2 (Y[0:96] -> X[0:96]) ============
        {
            float acc[2][3][4] = {};
            gemm_run<3,3>(gWc2, 96, sYhi, sYlo, LDY, 0, sWS, ng*24, acc, tid, lane, mg);
            mlp_epi<3>(acc, sCB2, ng*24, sXhi, sXlo, LDX, 0, lane, mg);
        }
        // ================= param MLP layer 1 (X[96:256] -> Y[0:160]) =========
        {
            float acc[2][5][4] = {};
            gemm_run<5,5>(gWp1, 160, sXhi, sXlo, LDX, 96, sWS, ng*40, acc, tid, lane, mg);
            mlp_epi<5>(acc, sPB1, ng*40, sYhi, sYlo, LDY, 0, lane, mg);
        }
        // ================= param MLP layer 2 (Y[0:160] -> X[96:256]) =========
        {
            float acc[2][5][4] = {};
            gemm_run<5,5>(gWp2, 160, sYhi, sYlo, LDY, 0, sWS, ng*40, acc, tid, lane, mg);
            mlp_epi<5>(acc, sPB2, ng*40, sXhi, sXlo, LDX, 96, lane, mg);
        }
        __syncthreads();
        // ---- per-head score sums from y2 (hi+lo reconstruction) ----
        for (int tau = tid; tau < KT*16; tau += NTHR) {
            const int r = tau >> 4;
            const int rest = tau & 15;
            const int h = rest >> 1;
            float s = 0.f;
            if ((rest & 1) == 0) {
                const int base = r*LDX + h*12;
                #pragma unroll
                for (int d = 0; d < 12; d++)
                    s += bf2f(sXhi[base+d]) + bf2f(sXlo[base+d]);
                sScC[(k0 + r)*H_ + h] = s;
            } else {
                const int base = r*LDX + 96 + h*20;
                #pragma unroll
                for (int d = 0; d < 20; d++)
                    s += bf2f(sXhi[base+d]) + bf2f(sXlo[base+d]);
                sScP[(k0 + r)*H_ + h] = s;
            }
        }
        // ================= out_e GEMM (X[0:256] -> 64) =======================
        {
            float acc[2][2][4] = {};
            gemm_run<2,8>(gWe, 64, sXhi, sXlo, LDX, 0, sWS, ng*16, acc, tid, lane, mg);
            #pragma unroll
            for (int mt = 0; mt < 2; mt++) {
                const int rb = mg*32 + mt*16 + g;
                #pragma unroll
                for (int nt = 0; nt < 2; nt++) {
                    const int c = ng*16 + nt*8 + 2*t4;
                    const float b0 = sBE[c], b1 = sBE[c+1];
                    float2 v0, v1;
                    v0.x = acc[mt][nt][0] + b0; v0.y = acc[mt][nt][1] + b1;
                    v1.x = acc[mt][nt][2] + b0; v1.y = acc[mt][nt][3] + b1;
                    *reinterpret_cast<float2*>(&outE[(size_t)(k0 + rb)*DE_ + c]) = v0;
                    *reinterpret_cast<float2*>(&outE[(size_t)(k0 + rb + 8)*DE_ + c]) = v1;
                }
            }
        }
    }
    __syncthreads();

    // ---- softmax over k per head (warp h owns head h) ----
    {
        const int h = warp;
        #pragma unroll
        for (int ty = 0; ty < 2; ty++) {
            float* S = ty ? sScP : sScC;
            float m = -1e30f;
            for (int k = lane; k < N_; k += 32) m = fmaxf(m, S[k*H_ + h]);
            #pragma unroll
            for (int o = 16; o; o >>= 1) m = fmaxf(m, __shfl_xor_sync(0xffffffffu, m, o));
            float sum = 0.f;
            for (int k = lane; k < N_; k += 32) {
                const float e = __expf(S[k*H_ + h] - m);
                S[k*H_ + h] = e;
                sum += e;
            }
            #pragma unroll
            for (int o = 16; o; o >>= 1) sum += __shfl_xor_sync(0xffffffffu, sum, o);
            const float inv = 1.f / sum;
            for (int k = lane; k < N_; k += 32) S[k*H_ + h] *= inv;
        }
    }
    __syncthreads();

    // ---- weighted V (cross: ap weights Vc, ac weights Vp) ----
    {
        float acc = 0.f;
        if (tid < DC_) {
            const int c = tid, h = c / 12;
            const float* V = g_Vc + (size_t)(b*N_) * DC_ + c;
            for (int k = 0; k < N_; k++) acc = fmaf(sScP[k*H_ + h], V[(size_t)k*DC_], acc);
        } else {
            const int p = tid - DC_, h = p / 20;
            const float* V = g_Vp + (size_t)(b*N_) * DP_ + p;
            for (int k = 0; k < N_; k++) acc = fmaf(sScC[k*H_ + h], V[(size_t)k*DP_], acc);
        }
        sWV[tid] = acc;
    }
    __syncthreads();

    // ---- output projections ----
    if (tid < DC_) {
        const int o = tid;
        float acc = bc_out[o];
        for (int c = 0; c < DC_; c++) acc = fmaf(sWV[c], wc_out[c*DC_ + o], acc);
        out[(size_t)bq*DC_ + o] = acc;
    } else {
        const int o = tid - DC_;
        float acc = bp_out[o];
        for (int p = 0; p < DP_; p++) acc = fmaf(sWV[DC_ + p], wp_out[p*DP_ + o], acc);
        out[(size_t)(B_*N_*DC_) + (size_t)bq*DP_ + o] = acc;
    }
}

// ============================= launch =============================
extern "C" void kernel_launch(void* const* d_in, const int* in_sizes, int n_in,
                              void* d_out, int out_size)
{
    const float* classes  = (const float*)d_in[0];
    const float* params   = (const float*)d_in[1];
    const float* edges    = (const float*)d_in[2];
    const float* wc_qkv   = (const float*)d_in[3];
    const float* bc_qkv   = (const float*)d_in[4];
    const float* wp_qkv   = (const float*)d_in[5];
    const float* bp_qkv   = (const float*)d_in[6];
    const float* fc_mul_w = (const float*)d_in[7];
    const float* fc_mul_b = (const float*)d_in[8];
    const float* fc_add_w = (const float*)d_in[9];
    const float* fc_add_b = (const float*)d_in[10];
    const float* fc_m1_w  = (const float*)d_in[11];
    const float* fc_m1_b  = (const float*)d_in[12];
    const float* fc_m2_w  = (const float*)d_in[13];
    const float* fc_m2_b  = (const float*)d_in[14];
    const float* fp_mul_w = (const float*)d_in[15];
    const float* fp_mul_b = (const float*)d_in[16];
    const float* fp_add_w = (const float*)d_in[17];
    const float* fp_add_b = (const float*)d_in[18];
    const float* fp_m1_w  = (const float*)d_in[19];
    const float* fp_m1_b  = (const float*)d_in[20];
    const float* fp_m2_w  = (const float*)d_in[21];
    const float* fp_m2_b  = (const float*)d_in[22];
    const float* wc_out   = (const float*)d_in[23];
    const float* bc_out   = (const float*)d_in[24];
    const float* wp_out   = (const float*)d_in[25];
    const float* bp_out   = (const float*)d_in[26];
    const float* we_out   = (const float*)d_in[27];
    const float* be_out   = (const float*)d_in[28];
    float* out = (float*)d_out;

    cudaFuncSetAttribute(fused_kernel,
                         cudaFuncAttributeMaxDynamicSharedMemorySize, SMEM_BYTES);

    const int pack_threads = 32768 + 18432 + 51200 + 16384;   // 118784
    pack_kernel<<<(pack_threads + NTHR - 1)/NTHR, NTHR>>>(
        fc_mul_w, fc_add_w, fc_m1_w, fc_m2_w,
        fp_mul_w, fp_add_w, fp_m1_w, fp_m2_w, we_out);
    prep_kernel<<<B_*N_, NTHR>>>(classes, params, wc_qkv, bc_qkv, wp_qkv, bp_qkv);
    fused_kernel<<<B_*N_, NTHR, SMEM_BYTES>>>(
        edges,
        fc_mul_b, fc_add_b, fc_m1_b, fc_m2_b,
        fp_mul_b, fp_add_b, fp_m1_b, fp_m2_b,
        wc_out, bc_out, wp_out, bp_out,
        be_out, out);
}

// round 8
// speedup vs baseline: 2.2423x; 1.3609x over previous
#include <cuda_runtime.h>
#include <cuda_bf16.h>
#include <cstdint>

#define NTHR 256
using ushort_t = unsigned short;

constexpr int B_  = 2;
constexpr int N_  = 256;
constexpr int DC_ = 96;
constexpr int DP_ = 160;
constexpr int DE_ = 64;
constexpr int H_  = 8;
constexpr int KT  = 64;        // k rows per tile
constexpr int NT_ = 4;         // tiles
constexpr int LDE = 72;        // bf16 elems
constexpr int LDX = 264;
constexpr int LDY = 200;
constexpr int LDWS = 40;       // staged weight row stride (ushorts): 16 hi + 16 lo + 8 pad
constexpr int WSB  = 20480;    // one weight buffer (bytes) = 256 rows * 80 B

// ---------------- device scratch (fp32) ----------------
__device__ float g_Qcat[B_*N_*256];   // [Qc*inv_sqrt96 | Qp*inv_sqrt160]
__device__ float g_Kcat[B_*N_*256];   // [Kc | Kp]
__device__ float g_Vc[B_*N_*DC_];
__device__ float g_Vp[B_*N_*DP_];

// ---------------- split-bf16 weights, contiguous K16 chunks ----------------
// addr: (k>>4)*(N*32) + n*32 + (k&15)  (hi), +16 (lo). Chunk = N*32 ush contiguous.
__device__ __align__(16) ushort_t gW1mul[4*256*32];   // K=64,  N=256 (cat)
__device__ __align__(16) ushort_t gW1add[4*256*32];
__device__ __align__(16) ushort_t gWc1[6*96*32];      // K=96,  N=96
__device__ __align__(16) ushort_t gWc2[6*96*32];
__device__ __align__(16) ushort_t gWp1[10*160*32];    // K=160, N=160
__device__ __align__(16) ushort_t gWp2[10*160*32];
__device__ __align__(16) ushort_t gWe[16*64*32];      // K=256 (permuted), N=64

// ---------------- shared memory byte offsets ----------------
constexpr int OFFB_Q   = 0;        // 256 f
constexpr int OFFB_WV  = 1024;     // 256 f
constexpr int OFFB_SCC = 2048;     // 2048 f
constexpr int OFFB_SCP = 10240;    // 2048 f
constexpr int OFFB_MB  = 18432;    // 256 f
constexpr int OFFB_AB  = 19456;    // 256 f
constexpr int OFFB_CB1 = 20480;    // 96 f
constexpr int OFFB_CB2 = 20864;
constexpr int OFFB_PB1 = 21248;    // 160 f
constexpr int OFFB_PB2 = 21888;
constexpr int OFFB_BE  = 22528;    // 64 f
constexpr int OFFB_EHI = 22784;    // 64*72 bf16 = 9216 B
constexpr int OFFB_ELO = 32000;
constexpr int OFFB_XHI = 41216;    // 64*264 bf16 = 33792 B
constexpr int OFFB_XLO = 75008;
constexpr int OFFB_YHI = 108800;   // 64*200 bf16 = 25600 B
constexpr int OFFB_YLO = 134400;
constexpr int OFFB_WS  = 160000;   // 2 * 20480 B ping-pong weight buffers
constexpr int SMEM_BYTES = 200960;

// ---------------- helpers ----------------
__device__ __forceinline__ float bf2f(ushort_t u) {
    return __uint_as_float(((unsigned)u) << 16);
}
__device__ __forceinline__ void split2(float x0, float x1, unsigned& hi, unsigned& lo) {
    const ushort_t h0 = __bfloat16_as_ushort(__float2bfloat16_rn(x0));
    const ushort_t h1 = __bfloat16_as_ushort(__float2bfloat16_rn(x1));
    const ushort_t l0 = __bfloat16_as_ushort(__float2bfloat16_rn(x0 - bf2f(h0)));
    const ushort_t l1 = __bfloat16_as_ushort(__float2bfloat16_rn(x1 - bf2f(h1)));
    hi = (unsigned)h0 | ((unsigned)h1 << 16);
    lo = (unsigned)l0 | ((unsigned)l1 << 16);
}
__device__ __forceinline__ void mma_bf16(float (&d)[4], const unsigned (&a)[4],
                                         const unsigned (&b)[2]) {
    asm("mma.sync.aligned.m16n8k16.row.col.f32.bf16.bf16.f32 "
        "{%0,%1,%2,%3},{%4,%5,%6,%7},{%8,%9},{%0,%1,%2,%3};"
        : "+f"(d[0]), "+f"(d[1]), "+f"(d[2]), "+f"(d[3])
        : "r"(a[0]), "r"(a[1]), "r"(a[2]), "r"(a[3]), "r"(b[0]), "r"(b[1]));
}
__device__ __forceinline__ float lrelu(float v) { return v > 0.f ? v : 0.05f * v; }

__device__ __forceinline__ uint32_t smem_u32(const void* p) {
    uint32_t a;
    asm("{ .reg .u64 t; cvta.to.shared.u64 t, %1; cvt.u32.u64 %0, t; }"
        : "=r"(a) : "l"(p));
    return a;
}
__device__ __forceinline__ void cpa16(uint32_t dst, const void* src) {
    asm volatile("cp.async.cg.shared.global [%0], [%1], 16;"
                 :: "r"(dst), "l"(src) : "memory");
}
#define CPA_COMMIT  asm volatile("cp.async.commit_group;" ::: "memory")
#define CPA_WAIT1   asm volatile("cp.async.wait_group 1;" ::: "memory")
#define CPA_WAIT0   asm volatile("cp.async.wait_group 0;" ::: "memory")

// global weight address (hi element; lo at +16)
__device__ __forceinline__ int waddr(int k, int n, int N) {
    return (k >> 4) * (N * 32) + n * 32 + (k & 15);
}

// ============================= prep: QKV =============================
__global__ void __launch_bounds__(NTHR) prep_kernel(
    const float* __restrict__ classes, const float* __restrict__ params,
    const float* __restrict__ wc_qkv,  const float* __restrict__ bc_qkv,
    const float* __restrict__ wp_qkv,  const float* __restrict__ bp_qkv)
{
    __shared__ float rc[DC_];
    __shared__ float rp[DP_];
    const int bn = blockIdx.x;
    const int t  = threadIdx.x;
    if (t < DC_) rc[t] = classes[bn*DC_ + t];
    if (t < DP_) rp[t] = params[bn*DP_ + t];
    __syncthreads();

    const float invc = 0.10206207261596575f;   // 1/sqrt(96)
    const float invp = 0.07905694150420949f;   // 1/sqrt(160)

    for (int o = t; o < 3*DC_; o += NTHR) {
        float acc = bc_qkv[o];
        #pragma unroll 4
        for (int i = 0; i < DC_; i++) acc = fmaf(rc[i], wc_qkv[i*3*DC_ + o], acc);
        const int part = o / DC_, d = o - part*DC_;
        if (part == 0)      g_Qcat[bn*256 + d] = acc * invc;
        else if (part == 1) g_Kcat[bn*256 + d] = acc;
        else                g_Vc[bn*DC_ + d] = acc;
    }
    for (int o = t; o < 3*DP_; o += NTHR) {
        float acc = bp_qkv[o];
        #pragma unroll 4
        for (int i = 0; i < DP_; i++) acc = fmaf(rp[i], wp_qkv[i*3*DP_ + o], acc);
        const int part = o / DP_, d = o - part*DP_;
        if (part == 0)      g_Qcat[bn*256 + 96 + d] = acc * invp;
        else if (part == 1) g_Kcat[bn*256 + 96 + d] = acc;
        else                g_Vp[bn*DP_ + d] = acc;
    }
}

// ============================= prep: weight split/pack =============================
__global__ void __launch_bounds__(NTHR) pack_kernel(
    const float* __restrict__ fc_mul_w, const float* __restrict__ fc_add_w,
    const float* __restrict__ fc_m1_w,  const float* __restrict__ fc_m2_w,
    const float* __restrict__ fp_mul_w, const float* __restrict__ fp_add_w,
    const float* __restrict__ fp_m1_w,  const float* __restrict__ fp_m2_w,
    const float* __restrict__ we_out)
{
    int i = blockIdx.x * NTHR + threadIdx.x;
    float v; ushort_t* dst; int addr;
    if (i < 32768) {                                   // W1 mul/add, K=64 N=256
        const bool isAdd = i >= 16384;
        const int t = i & 16383, k = t >> 8, n = t & 255;
        if (n < 96) v = (isAdd ? fc_add_w : fc_mul_w)[k*96 + n];
        else        v = (isAdd ? fp_add_w : fp_mul_w)[k*160 + n - 96];
        dst = isAdd ? gW1add : gW1mul; addr = waddr(k, n, 256);
    } else if ((i -= 32768) < 18432) {                 // Wc m1/m2, K=96 N=96
        const bool l2 = i >= 9216;
        const int t = l2 ? i - 9216 : i, k = t / 96, n = t % 96;
        v = (l2 ? fc_m2_w : fc_m1_w)[k*96 + n];
        dst = l2 ? gWc2 : gWc1; addr = waddr(k, n, 96);
    } else if ((i -= 18432) < 51200) {                 // Wp m1/m2, K=160 N=160
        const bool l2 = i >= 25600;
        const int t = l2 ? i - 25600 : i, k = t / 160, n = t % 160;
        v = (l2 ? fp_m2_w : fp_m1_w)[k*160 + n];
        dst = l2 ? gWp2 : gWp1; addr = waddr(k, n, 160);
    } else if ((i -= 51200) < 16384) {                 // We, K=256 (permuted) N=64
        const int k = i >> 6, n = i & 63;
        const int src = k < 96 ? (k/12)*32 + (k%12)
                               : ((k-96)/20)*32 + 12 + ((k-96)%20);
        v = we_out[src*64 + n];
        dst = gWe; addr = waddr(k, n, 64);
    } else return;
    const ushort_t h = __bfloat16_as_ushort(__float2bfloat16_rn(v));
    const ushort_t l = __bfloat16_as_ushort(__float2bfloat16_rn(v - bf2f(h)));
    dst[addr]      = h;
    dst[addr + 16] = l;
}

// ---------------- A fragment load (row-major bf16) ----------------
__device__ __forceinline__ void ldA(unsigned (&A)[4], const ushort_t* base,
                                    int lda, int row, int col) {
    const ushort_t* p = base + row*lda + col;
    A[0] = *reinterpret_cast<const unsigned*>(p);
    A[1] = *reinterpret_cast<const unsigned*>(p + 8*lda);
    A[2] = *reinterpret_cast<const unsigned*>(p + 8);
    A[3] = *reinterpret_cast<const unsigned*>(p + 8*lda + 8);
}

// ---------------- one K=16 chunk, 3-product split mma ----------------
template<int NTILES>
__device__ __forceinline__ void mma_chunk16(
    const ushort_t* __restrict__ Ahi, const ushort_t* __restrict__ Alo,
    int lda, int acol,
    const ushort_t* __restrict__ W, int nb,
    float (&acc)[2][NTILES][4], int lane, int mg)
{
    const int g = lane >> 2, t = lane & 3;
    unsigned Ah[2][4], Al[2][4];
    #pragma unroll
    for (int mt = 0; mt < 2; mt++) {
        const int row = mg*32 + mt*16 + g;
        const int col = acol + 2*t;
        ldA(Ah[mt], Ahi, lda, row, col);
        ldA(Al[mt], Alo, lda, row, col);
    }
    #pragma unroll
    for (int nt = 0; nt < NTILES; nt++) {
        const ushort_t* wp = W + (nb + nt*8 + g)*LDWS + 2*t;
        unsigned Bh[2], Bl[2];
        Bh[0] = *reinterpret_cast<const unsigned*>(wp);
        Bh[1] = *reinterpret_cast<const unsigned*>(wp + 8);
        Bl[0] = *reinterpret_cast<const unsigned*>(wp + 16);
        Bl[1] = *reinterpret_cast<const unsigned*>(wp + 24);
        #pragma unroll
        for (int mt = 0; mt < 2; mt++) {
            mma_bf16(acc[mt][nt], Ah[mt], Bh);
            mma_bf16(acc[mt][nt], Ah[mt], Bl);
            mma_bf16(acc[mt][nt], Al[mt], Bh);
        }
    }
}

// ---------------- cp.async chunk prefetch (K16 chunk = Nrows * 64 B) --------
__device__ __forceinline__ void prefetch_chunk(const ushort_t* __restrict__ gW,
                                               int ch, int Nrows,
                                               uint32_t dstaddr, int tid)
{
    const ushort_t* src = gW + ch * Nrows * 32;
    for (int u = tid; u < Nrows * 4; u += NTHR) {
        const int n = u >> 2, q = u & 3;
        cpa16(dstaddr + n*80 + q*16, src + n*32 + q*8);
    }
    CPA_COMMIT;
}

// ---------------- pipelined GEMM driver ----------------
template<int NTILES, int NCH>
__device__ __forceinline__ void gemm_run(
    const ushort_t* __restrict__ gW, int Nrows,
    const ushort_t* __restrict__ Ahi, const ushort_t* __restrict__ Alo,
    int lda, int abase,
    ushort_t* sWS, uint32_t wsaddr, int nb, float (&acc)[2][NTILES][4],
    int tid, int lane, int mg)
{
    prefetch_chunk(gW, 0, Nrows, wsaddr, tid);
    #pragma unroll 1
    for (int ch = 0; ch < NCH; ch++) {
        if (ch + 1 < NCH) {
            prefetch_chunk(gW, ch + 1, Nrows, wsaddr + ((ch + 1) & 1) * WSB, tid);
            CPA_WAIT1;
        } else {
            CPA_WAIT0;
        }
        __syncthreads();
        mma_chunk16<NTILES>(Ahi, Alo, lda, abase + ch*16,
                            sWS + (ch & 1) * (WSB/2), nb, acc, lane, mg);
        __syncthreads();
    }
}

// ---------------- MLP epilogue: lrelu(acc + bias) -> split store ----------------
template<int NTILES>
__device__ __forceinline__ void mlp_epi(
    float (&acc)[2][NTILES][4], const float* __restrict__ bias, int nbase,
    ushort_t* __restrict__ Dhi, ushort_t* __restrict__ Dlo, int ldd, int coff,
    int lane, int mg)
{
    const int g = lane >> 2, t = lane & 3;
    #pragma unroll
    for (int mt = 0; mt < 2; mt++) {
        const int rb = mg*32 + mt*16 + g;
        #pragma unroll
        for (int nt = 0; nt < NTILES; nt++) {
            const int c = nbase + nt*8 + 2*t;
            const float b0 = bias[c], b1 = bias[c+1];
            unsigned h, l;
            split2(lrelu(acc[mt][nt][0] + b0), lrelu(acc[mt][nt][1] + b1), h, l);
            *reinterpret_cast<unsigned*>(&Dhi[rb*ldd + coff + c]) = h;
            *reinterpret_cast<unsigned*>(&Dlo[rb*ldd + coff + c]) = l;
            split2(lrelu(acc[mt][nt][2] + b0), lrelu(acc[mt][nt][3] + b1), h, l);
            *reinterpret_cast<unsigned*>(&Dhi[(rb+8)*ldd + coff + c]) = h;
            *reinterpret_cast<unsigned*>(&Dlo[(rb+8)*ldd + coff + c]) = l;
        }
    }
}

// ============================= fused main kernel =============================
__global__ void __launch_bounds__(NTHR, 1) fused_kernel(
    const float* __restrict__ edges,
    const float* __restrict__ fc_mul_b, const float* __restrict__ fc_add_b,
    const float* __restrict__ fc_m1_b,  const float* __restrict__ fc_m2_b,
    const float* __restrict__ fp_mul_b, const float* __restrict__ fp_add_b,
    const float* __restrict__ fp_m1_b,  const float* __restrict__ fp_m2_b,
    const float* __restrict__ wc_out,   const float* __restrict__ bc_out,
    const float* __restrict__ wp_out,   const float* __restrict__ bp_out,
    const float* __restrict__ be_out,
    float* __restrict__ out)
{
    extern __shared__ char smc[];
    float* sQ   = reinterpret_cast<float*>(smc + OFFB_Q);
    float* sWV  = reinterpret_cast<float*>(smc + OFFB_WV);
    float* sScC = reinterpret_cast<float*>(smc + OFFB_SCC);
    float* sScP = reinterpret_cast<float*>(smc + OFFB_SCP);
    float* sMB  = reinterpret_cast<float*>(smc + OFFB_MB);
    float* sAB  = reinterpret_cast<float*>(smc + OFFB_AB);
    float* sCB1 = reinterpret_cast<float*>(smc + OFFB_CB1);
    float* sCB2 = reinterpret_cast<float*>(smc + OFFB_CB2);
    float* sPB1 = reinterpret_cast<float*>(smc + OFFB_PB1);
    float* sPB2 = reinterpret_cast<float*>(smc + OFFB_PB2);
    float* sBE  = reinterpret_cast<float*>(smc + OFFB_BE);
    ushort_t* sEhi = reinterpret_cast<ushort_t*>(smc + OFFB_EHI);
    ushort_t* sElo = reinterpret_cast<ushort_t*>(smc + OFFB_ELO);
    ushort_t* sXhi = reinterpret_cast<ushort_t*>(smc + OFFB_XHI);
    ushort_t* sXlo = reinterpret_cast<ushort_t*>(smc + OFFB_XLO);
    ushort_t* sYhi = reinterpret_cast<ushort_t*>(smc + OFFB_YHI);
    ushort_t* sYlo = reinterpret_cast<ushort_t*>(smc + OFFB_YLO);
    ushort_t* sWS  = reinterpret_cast<ushort_t*>(smc + OFFB_WS);
    const uint32_t wsaddr = smem_u32(smc + OFFB_WS);

    const int tid  = threadIdx.x;
    const int warp = tid >> 5;
    const int lane = tid & 31;
    const int mg   = warp >> 2;      // 0..1 row group (32 rows)
    const int ng   = warp & 3;       // 0..3 col group
    const int g    = lane >> 2, t4 = lane & 3;
    const int bq   = blockIdx.x;
    const int b    = bq >> 8;

    // persistent stages
    for (int i = tid; i < 256; i += NTHR) sQ[i] = g_Qcat[bq*256 + i];
    for (int i = tid; i < DC_; i += NTHR) {
        sMB[i]  = fc_mul_b[i];  sAB[i]  = fc_add_b[i];
        sCB1[i] = fc_m1_b[i];   sCB2[i] = fc_m2_b[i];
    }
    for (int i = tid; i < DP_; i += NTHR) {
        sMB[96+i] = fp_mul_b[i];  sAB[96+i] = fp_add_b[i];
        sPB1[i]   = fp_m1_b[i];   sPB2[i]   = fp_m2_b[i];
    }
    if (tid < DE_) sBE[tid] = be_out[tid];

    const float* Eb = edges + (size_t)bq * N_ * DE_;
    float* outE = out + (size_t)(B_*N_*DC_ + B_*N_*DP_) + (size_t)bq * N_ * DE_;

    for (int tt = 0; tt < NT_; tt++) {
        const int k0 = tt * KT;
        __syncthreads();
        // ---- load + split E tile ----
        for (int idx = tid; idx < KT*32; idx += NTHR) {
            const int r = idx >> 5, kp = (idx & 31) * 2;
            const float2 e2 = *reinterpret_cast<const float2*>(
                &Eb[(size_t)(k0 + r)*DE_ + kp]);
            unsigned h, l; split2(e2.x, e2.y, h, l);
            *reinterpret_cast<unsigned*>(&sEhi[r*LDE + kp]) = h;
            *reinterpret_cast<unsigned*>(&sElo[r*LDE + kp]) = l;
        }
        // ========== stage 1 pass A: m = E @ Wmul + mb  -> split-store to X ====
        {
            float acc[2][8][4] = {};
            gemm_run<8,4>(gW1mul, 256, sEhi, sElo, LDE, 0, sWS, wsaddr, ng*64,
                          acc, tid, lane, mg);
            #pragma unroll
            for (int mt = 0; mt < 2; mt++) {
                const int rb = mg*32 + mt*16 + g;
                #pragma unroll
                for (int nt = 0; nt < 8; nt++) {
                    const int c = ng*64 + nt*8 + 2*t4;
                    const float mb0 = sMB[c], mb1 = sMB[c+1];
                    #pragma unroll
                    for (int hh = 0; hh < 2; hh++) {
                        const int r = rb + hh*8;
                        unsigned h, l;
                        split2(acc[mt][nt][2*hh+0] + mb0,
                               acc[mt][nt][2*hh+1] + mb1, h, l);
                        *reinterpret_cast<unsigned*>(&sXhi[r*LDX + c]) = h;
                        *reinterpret_cast<unsigned*>(&sXlo[r*LDX + c]) = l;
                    }
                }
            }
        }
        // ========== stage 1 pass B: add-GEMM + FiLM epilogue (reads m from X) ==
        {
            float acc[2][8][4] = {};
            gemm_run<8,4>(gW1add, 256, sEhi, sElo, LDE, 0, sWS, wsaddr, ng*64,
                          acc, tid, lane, mg);
            #pragma unroll
            for (int mt = 0; mt < 2; mt++) {
                const int rb = mg*32 + mt*16 + g;
                #pragma unroll
                for (int nt = 0; nt < 8; nt++) {
                    const int c = ng*64 + nt*8 + 2*t4;
                    const float q0 = sQ[c], q1 = sQ[c+1];
                    const float ab0 = sAB[c], ab1 = sAB[c+1];
                    #pragma unroll
                    for (int hh = 0; hh < 2; hh++) {
                        const int r = rb + hh*8;
                        const float m0 = bf2f(sXhi[r*LDX + c])
                                       + bf2f(sXlo[r*LDX + c]);
                        const float m1 = bf2f(sXhi[r*LDX + c + 1])
                                       + bf2f(sXlo[r*LDX + c + 1]);
                        const float2 kv = *reinterpret_cast<const float2*>(
                            &g_Kcat[(size_t)(b*N_ + k0 + r)*256 + c]);
                        const float a0 = q0 * kv.x, a1 = q1 * kv.y;
                        const float x0 = fmaf(a0, m0, acc[mt][nt][2*hh+0] + ab0 + a0);
                        const float x1 = fmaf(a1, m1, acc[mt][nt][2*hh+1] + ab1 + a1);
                        unsigned h, l; split2(x0, x1, h, l);
                        *reinterpret_cast<unsigned*>(&sXhi[r*LDX + c]) = h;
                        *reinterpret_cast<unsigned*>(&sXlo[r*LDX + c]) = l;
                    }
                }
            }
        }
        // ================= class MLP layer 1 (X[0:96] -> Y[0:96]) ============
        {
            float acc[2][3][4] = {};
            gemm_run<3,6>(gWc1, 96, sXhi, sXlo, LDX, 0, sWS, wsaddr, ng*24,
                          acc, tid, lane, mg);
            mlp_epi<3>(acc, sCB1, ng*24, sYhi, sYlo, LDY, 0, lane, mg);
        }
        // ================= class MLP layer 2 (Y[0:96] -> X[0:96]) ============
        {
            float acc[2][3][4] = {};
            gemm_run<3,6>(gWc2, 96, sYhi, sYlo, LDY, 0, sWS, wsaddr, ng*24,
                          acc, tid, lane, mg);
            mlp_epi<3>(acc, sCB2, ng*24, sXhi, sXlo, LDX, 0, lane, mg);
        }
        // ================= param MLP layer 1 (X[96:256] -> Y[0:160]) =========
        {
            float acc[2][5][4] = {};
            gemm_run<5,10>(gWp1, 160, sXhi, sXlo, LDX, 96, sWS, wsaddr, ng*40,
                           acc, tid, lane, mg);
            mlp_epi<5>(acc, sPB1, ng*40, sYhi, sYlo, LDY, 0, lane, mg);
        }
        // ================= param MLP layer 2 (Y[0:160] -> X[96:256]) =========
        {
            float acc[2][5][4] = {};
            gemm_run<5,10>(gWp2, 160, sYhi, sYlo, LDY, 0, sWS, wsaddr, ng*40,
                           acc, tid, lane, mg);
            mlp_epi<5>(acc, sPB2, ng*40, sXhi, sXlo, LDX, 96, lane, mg);
        }
        __syncthreads();
        // ---- per-head score sums from y2 (hi+lo reconstruction) ----
        for (int tau = tid; tau < KT*16; tau += NTHR) {
            const int r = tau >> 4;
            const int rest = tau & 15;
            const int h = rest >> 1;
            float s = 0.f;
            if ((rest & 1) == 0) {
                const int base = r*LDX + h*12;
                #pragma unroll
                for (int d = 0; d < 12; d++)
                    s += bf2f(sXhi[base+d]) + bf2f(sXlo[base+d]);
                sScC[(k0 + r)*H_ + h] = s;
            } else {
                const int base = r*LDX + 96 + h*20;
                #pragma unroll
                for (int d = 0; d < 20; d++)
                    s += bf2f(sXhi[base+d]) + bf2f(sXlo[base+d]);
                sScP[(k0 + r)*H_ + h] = s;
            }
        }
        // ================= out_e GEMM (X[0:256] -> 64) =======================
        {
            float acc[2][2][4] = {};
            gemm_run<2,16>(gWe, 64, sXhi, sXlo, LDX, 0, sWS, wsaddr, ng*16,
                           acc, tid, lane, mg);
            #pragma unroll
            for (int mt = 0; mt < 2; mt++) {
                const int rb = mg*32 + mt*16 + g;
                #pragma unroll
                for (int nt = 0; nt < 2; nt++) {
                    const int c = ng*16 + nt*8 + 2*t4;
                    const float b0 = sBE[c], b1 = sBE[c+1];
                    float2 v0, v1;
                    v0.x = acc[mt][nt][0] + b0; v0.y = acc[mt][nt][1] + b1;
                    v1.x = acc[mt][nt][2] + b0; v1.y = acc[mt][nt][3] + b1;
                    *reinterpret_cast<float2*>(&outE[(size_t)(k0 + rb)*DE_ + c]) = v0;
                    *reinterpret_cast<float2*>(&outE[(size_t)(k0 + rb + 8)*DE_ + c]) = v1;
                }
            }
        }
    }
    __syncthreads();

    // ---- softmax over k per head (warp h owns head h) ----
    {
        const int h = warp;
        #pragma unroll
        for (int ty = 0; ty < 2; ty++) {
            float* S = ty ? sScP : sScC;
            float m = -1e30f;
            for (int k = lane; k < N_; k += 32) m = fmaxf(m, S[k*H_ + h]);
            #pragma unroll
            for (int o = 16; o; o >>= 1) m = fmaxf(m, __shfl_xor_sync(0xffffffffu, m, o));
            float sum = 0.f;
            for (int k = lane; k < N_; k += 32) {
                const float e = __expf(S[k*H_ + h] - m);
                S[k*H_ + h] = e;
                sum += e;
            }
            #pragma unroll
            for (int o = 16; o; o >>= 1) sum += __shfl_xor_sync(0xffffffffu, sum, o);
            const float inv = 1.f / sum;
            for (int k = lane; k < N_; k += 32) S[k*H_ + h] *= inv;
        }
    }
    __syncthreads();

    // ---- weighted V (cross: ap weights Vc, ac weights Vp) ----
    {
        float acc = 0.f;
        if (tid < DC_) {
            const int c = tid, h = c / 12;
            const float* V = g_Vc + (size_t)(b*N_) * DC_ + c;
            for (int k = 0; k < N_; k++) acc = fmaf(sScP[k*H_ + h], V[(size_t)k*DC_], acc);
        } else {
            const int p = tid - DC_, h = p / 20;
            const float* V = g_Vp + (size_t)(b*N_) * DP_ + p;
            for (int k = 0; k < N_; k++) acc = fmaf(sScC[k*H_ + h], V[(size_t)k*DP_], acc);
        }
        sWV[tid] = acc;
    }
    __syncthreads();

    // ---- output projections ----
    if (tid < DC_) {
        const int o = tid;
        float acc = bc_out[o];
        for (int c = 0; c < DC_; c++) acc = fmaf(sWV[c], wc_out[c*DC_ + o], acc);
        out[(size_t)bq*DC_ + o] = acc;
    } else {
        const int o = tid - DC_;
        float acc = bp_out[o];
        for (int p = 0; p < DP_; p++) acc = fmaf(sWV[DC_ + p], wp_out[p*DP_ + o], acc);
        out[(size_t)(B_*N_*DC_) + (size_t)bq*DP_ + o] = acc;
    }
}

// ============================= launch =============================
extern "C" void kernel_launch(void* const* d_in, const int* in_sizes, int n_in,
                              void* d_out, int out_size)
{
    const float* classes  = (const float*)d_in[0];
    const float* params   = (const float*)d_in[1];
    const float* edges    = (const float*)d_in[2];
    const float* wc_qkv   = (const float*)d_in[3];
    const float* bc_qkv   = (const float*)d_in[4];
    const float* wp_qkv   = (const float*)d_in[5];
    const float* bp_qkv   = (const float*)d_in[6];
    const float* fc_mul_w = (const float*)d_in[7];
    const float* fc_mul_b = (const float*)d_in[8];
    const float* fc_add_w = (const float*)d_in[9];
    const float* fc_add_b = (const float*)d_in[10];
    const float* fc_m1_w  = (const float*)d_in[11];
    const float* fc_m1_b  = (const float*)d_in[12];
    const float* fc_m2_w  = (const float*)d_in[13];
    const float* fc_m2_b  = (const float*)d_in[14];
    const float* fp_mul_w = (const float*)d_in[15];
    const float* fp_mul_b = (const float*)d_in[16];
    const float* fp_add_w = (const float*)d_in[17];
    const float* fp_add_b = (const float*)d_in[18];
    const float* fp_m1_w  = (const float*)d_in[19];
    const float* fp_m1_b  = (const float*)d_in[20];
    const float* fp_m2_w  = (const float*)d_in[21];
    const float* fp_m2_b  = (const float*)d_in[22];
    const float* wc_out   = (const float*)d_in[23];
    const float* bc_out   = (const float*)d_in[24];
    const float* wp_out   = (const float*)d_in[25];
    const float* bp_out   = (const float*)d_in[26];
    const float* we_out   = (const float*)d_in[27];
    const float* be_out   = (const float*)d_in[28];
    float* out = (float*)d_out;

    cudaFuncSetAttribute(fused_kernel,
                         cudaFuncAttributeMaxDynamicSharedMemorySize, SMEM_BYTES);

    const int pack_threads = 32768 + 18432 + 51200 + 16384;   // 118784
    pack_kernel<<<(pack_threads + NTHR - 1)/NTHR, NTHR>>>(
        fc_mul_w, fc_add_w, fc_m1_w, fc_m2_w,
        fp_mul_w, fp_add_w, fp_m1_w, fp_m2_w, we_out);
    prep_kernel<<<B_*N_, NTHR>>>(classes, params, wc_qkv, bc_qkv, wp_qkv, bp_qkv);
    fused_kernel<<<B_*N_, NTHR, SMEM_BYTES>>>(
        edges,
        fc_mul_b, fc_add_b, fc_m1_b, fc_m2_b,
        fp_mul_b, fp_add_b, fp_m1_b, fp_m2_b,
        wc_out, bc_out, wp_out, bp_out,
        be_out, out);
}